// round 1
// baseline (speedup 1.0000x reference)
#include <cuda_runtime.h>
#include <cuda_bf16.h>
#include <math.h>

// Problem constants
#define BB   2
#define LL   2048
#define DD   1024
#define HH   16
#define HD   64
#define MM   (BB*LL)          // 4096

// Scratch (static device memory -- no allocations allowed)
__device__ float g_Wfold[3 * DD * DD];    // folded Wq^T@R, Wk^T@R, Wv^T@R
__device__ float g_QKV[3 * MM * DD];      // Q, K, V  (M x D each)
__device__ float g_AO[MM * DD];           // attention output (M x D)

// ---------------------------------------------------------------------------
// Generic fp32 SGEMM:  C[M,N] = op(A) @ op(B)
//   op(A)[m][k] = TA ? A[k*lda+m] : A[m*lda+k]
//   op(B)[k][n] = TB ? B[n*ldb+k] : B[k*ldb+n]
// Requires M%128==0, N%128==0, K%8==0 (true for all uses here).
// 128x128x8 tile, 256 threads, 8x8 microtile.
// ---------------------------------------------------------------------------
template <bool TA, bool TB>
__global__ __launch_bounds__(256)
void sgemm_kernel(int M, int N, int K,
                  const float* __restrict__ A, int lda,
                  const float* __restrict__ B, int ldb,
                  float* __restrict__ C, int ldc)
{
    constexpr int BM = 128, BN = 128, BK = 8;
    __shared__ float As[BK][BM];
    __shared__ float Bs[BK][BN];

    const int tid = threadIdx.x;
    const int m0 = blockIdx.y * BM;
    const int n0 = blockIdx.x * BN;
    const int tx = tid & 15;        // 0..15 -> column group
    const int ty = tid >> 4;        // 0..15 -> row group

    float acc[8][8];
#pragma unroll
    for (int i = 0; i < 8; i++)
#pragma unroll
        for (int j = 0; j < 8; j++) acc[i][j] = 0.f;

    for (int k0 = 0; k0 < K; k0 += BK) {
        // ---- load A tile into As[k][m] ----
        if (!TA) {
            // A[m][k] rows: each thread loads one float4 along k
            const int row = tid >> 1;
            const int c4  = (tid & 1) * 4;
            float4 v = *reinterpret_cast<const float4*>(
                &A[(size_t)(m0 + row) * lda + k0 + c4]);
            As[c4 + 0][row] = v.x;
            As[c4 + 1][row] = v.y;
            As[c4 + 2][row] = v.z;
            As[c4 + 3][row] = v.w;
        } else {
            // op(A)[m][k] = A[k][m]: contiguous in m
            const int p  = tid >> 5;
            const int m4 = (tid & 31) * 4;
            float4 v = *reinterpret_cast<const float4*>(
                &A[(size_t)(k0 + p) * lda + m0 + m4]);
            *reinterpret_cast<float4*>(&As[p][m4]) = v;
        }
        // ---- load B tile into Bs[k][n] ----
        if (!TB) {
            const int p  = tid >> 5;
            const int n4 = (tid & 31) * 4;
            float4 v = *reinterpret_cast<const float4*>(
                &B[(size_t)(k0 + p) * ldb + n0 + n4]);
            *reinterpret_cast<float4*>(&Bs[p][n4]) = v;
        } else {
            // op(B)[k][n] = B[n][k]: contiguous in k
            const int row = tid >> 1;
            const int c4  = (tid & 1) * 4;
            float4 v = *reinterpret_cast<const float4*>(
                &B[(size_t)(n0 + row) * ldb + k0 + c4]);
            Bs[c4 + 0][row] = v.x;
            Bs[c4 + 1][row] = v.y;
            Bs[c4 + 2][row] = v.z;
            Bs[c4 + 3][row] = v.w;
        }
        __syncthreads();

#pragma unroll
        for (int p = 0; p < BK; p++) {
            float ar[8], br[8];
            *reinterpret_cast<float4*>(&ar[0]) =
                *reinterpret_cast<const float4*>(&As[p][ty * 8]);
            *reinterpret_cast<float4*>(&ar[4]) =
                *reinterpret_cast<const float4*>(&As[p][ty * 8 + 4]);
            *reinterpret_cast<float4*>(&br[0]) =
                *reinterpret_cast<const float4*>(&Bs[p][tx * 8]);
            *reinterpret_cast<float4*>(&br[4]) =
                *reinterpret_cast<const float4*>(&Bs[p][tx * 8 + 4]);
#pragma unroll
            for (int i = 0; i < 8; i++)
#pragma unroll
                for (int j = 0; j < 8; j++)
                    acc[i][j] = fmaf(ar[i], br[j], acc[i][j]);
        }
        __syncthreads();
    }

    // ---- store ----
#pragma unroll
    for (int i = 0; i < 8; i++) {
        float* cp = &C[(size_t)(m0 + ty * 8 + i) * ldc + n0 + tx * 8];
        float4 v0 = make_float4(acc[i][0], acc[i][1], acc[i][2], acc[i][3]);
        float4 v1 = make_float4(acc[i][4], acc[i][5], acc[i][6], acc[i][7]);
        *reinterpret_cast<float4*>(cp)     = v0;
        *reinterpret_cast<float4*>(cp + 4) = v1;
    }
}

// ---------------------------------------------------------------------------
// Flash-style attention.
// Q,K,V stored as (M=B*L, D) row-major; head h occupies columns [h*64, h*64+64).
// Grid: (L/128, H, B). 128 threads; each thread owns one q row entirely:
// q and the 64-wide output accumulator live in registers, online softmax is
// thread-local (no cross-thread reductions). K/V tiles are SMEM broadcasts.
// ---------------------------------------------------------------------------
#define QT 128
#define KT 32

__global__ __launch_bounds__(QT)
void flash_attn_kernel(const float* __restrict__ Q,
                       const float* __restrict__ K,
                       const float* __restrict__ V,
                       const float* __restrict__ entangle,
                       float* __restrict__ O)
{
    const int b = blockIdx.z;
    const int h = blockIdx.y;
    const int q0 = blockIdx.x * QT;
    const int row = threadIdx.x;

    const float scale = entangle[h] * 0.125f;  // / sqrt(64)

    const size_t m = (size_t)b * LL + q0 + row;
    const float* qptr = Q + m * DD + h * HD;

    float q[HD];
#pragma unroll
    for (int d = 0; d < HD; d++) q[d] = qptr[d] * scale;

    float acc[HD];
#pragma unroll
    for (int d = 0; d < HD; d++) acc[d] = 0.f;
    float mi = -INFINITY;
    float li = 0.f;

    __shared__ float Ks[KT][HD];
    __shared__ float Vs[KT][HD];

    const float* Kp = K + ((size_t)b * LL) * DD + h * HD;
    const float* Vp = V + ((size_t)b * LL) * DD + h * HD;

    for (int k0 = 0; k0 < LL; k0 += KT) {
        __syncthreads();
        // load KT x 64 tiles of K and V (float4, coalesced)
#pragma unroll
        for (int it = 0; it < (KT * HD / 4) / QT; it++) {
            int idx = threadIdx.x + it * QT;
            int j = idx >> 4;          // / (HD/4)
            int c = idx & 15;
            *reinterpret_cast<float4*>(&Ks[j][c * 4]) =
                *reinterpret_cast<const float4*>(&Kp[(size_t)(k0 + j) * DD + c * 4]);
            *reinterpret_cast<float4*>(&Vs[j][c * 4]) =
                *reinterpret_cast<const float4*>(&Vp[(size_t)(k0 + j) * DD + c * 4]);
        }
        __syncthreads();

        float s[KT];
        float mnew = mi;
#pragma unroll
        for (int j = 0; j < KT; j++) {
            const float4* k4 = reinterpret_cast<const float4*>(&Ks[j][0]);
            float sum = 0.f;
#pragma unroll
            for (int c = 0; c < HD / 4; c++) {
                float4 kv = k4[c];
                sum = fmaf(q[4 * c + 0], kv.x, sum);
                sum = fmaf(q[4 * c + 1], kv.y, sum);
                sum = fmaf(q[4 * c + 2], kv.z, sum);
                sum = fmaf(q[4 * c + 3], kv.w, sum);
            }
            s[j] = sum;
            mnew = fmaxf(mnew, sum);
        }

        if (mnew > mi) {
            float corr = __expf(mi - mnew);
            li *= corr;
#pragma unroll
            for (int d = 0; d < HD; d++) acc[d] *= corr;
            mi = mnew;
        }

#pragma unroll
        for (int j = 0; j < KT; j++) {
            float p = __expf(s[j] - mi);
            li += p;
            const float4* v4 = reinterpret_cast<const float4*>(&Vs[j][0]);
#pragma unroll
            for (int c = 0; c < HD / 4; c++) {
                float4 vv = v4[c];
                acc[4 * c + 0] = fmaf(p, vv.x, acc[4 * c + 0]);
                acc[4 * c + 1] = fmaf(p, vv.y, acc[4 * c + 1]);
                acc[4 * c + 2] = fmaf(p, vv.z, acc[4 * c + 2]);
                acc[4 * c + 3] = fmaf(p, vv.w, acc[4 * c + 3]);
            }
        }
    }

    const float inv = 1.f / li;
    float* optr = O + m * DD + h * HD;
#pragma unroll
    for (int c = 0; c < HD / 4; c++) {
        float4 v = make_float4(acc[4 * c + 0] * inv, acc[4 * c + 1] * inv,
                               acc[4 * c + 2] * inv, acc[4 * c + 3] * inv);
        *reinterpret_cast<float4*>(&optr[4 * c]) = v;
    }
}

// ---------------------------------------------------------------------------
// Launch
// ---------------------------------------------------------------------------
extern "C" void kernel_launch(void* const* d_in, const int* in_sizes, int n_in,
                              void* d_out, int out_size)
{
    const float* X   = (const float*)d_in[0];   // (B, L, D)
    const float* R   = (const float*)d_in[1];   // (D, D)
    const float* ent = (const float*)d_in[2];   // (H,)
    const float* Wq  = (const float*)d_in[3];
    const float* Wk  = (const float*)d_in[4];
    const float* Wv  = (const float*)d_in[5];
    const float* Wo  = (const float*)d_in[6];
    float* out = (float*)d_out;

    float *wfold, *qkv, *ao;
    cudaGetSymbolAddress((void**)&wfold, g_Wfold);
    cudaGetSymbolAddress((void**)&qkv,   g_QKV);
    cudaGetSymbolAddress((void**)&ao,    g_AO);

    dim3 blk(256);
    dim3 gridW(DD / 128, DD / 128);     // 8x8
    dim3 gridP(DD / 128, MM / 128);     // 8x32

    const float* W[3] = {Wq, Wk, Wv};
    // 1) Fold weights: Wfold_i = W_i^T @ R   (TA=true, TB=false)
    for (int i = 0; i < 3; i++) {
        sgemm_kernel<true, false><<<gridW, blk>>>(
            DD, DD, DD, W[i], DD, R, DD, wfold + (size_t)i * DD * DD, DD);
    }
    // 2) Projections: QKV_i = X @ Wfold_i    (NN)
    for (int i = 0; i < 3; i++) {
        sgemm_kernel<false, false><<<gridP, blk>>>(
            MM, DD, DD, X, DD, wfold + (size_t)i * DD * DD, DD,
            qkv + (size_t)i * MM * DD, DD);
    }
    // 3) Attention
    dim3 gridA(LL / QT, HH, BB);
    flash_attn_kernel<<<gridA, QT>>>(qkv,
                                     qkv + (size_t)MM * DD,
                                     qkv + (size_t)2 * MM * DD,
                                     ent, ao);
    // 4) Output projection: out = AO @ Wo^T  (TB=true)
    sgemm_kernel<false, true><<<gridP, blk>>>(
        MM, DD, DD, ao, DD, Wo, DD, out, DD);
}

// round 3
// speedup vs baseline: 1.1063x; 1.1063x over previous
#include <cuda_runtime.h>
#include <cuda_bf16.h>
#include <math.h>
#include <stdint.h>

// Problem constants
#define BB   2
#define LL   2048
#define DD   1024
#define HH   16
#define HD   64
#define MM   (BB*LL)          // 4096
#define QKV_LD (3*DD)         // fused QKV row stride

// Scratch (static device memory -- no allocations allowed)
__device__ float g_WfoldT[3 * DD * DD];   // R^T @ W_i  ([n][k] B-operand layout)
__device__ float g_QKV[MM * 3 * DD];      // fused [M][3072]: Q | K | V
__device__ float g_AO[MM * DD];           // attention output (M x D)

// ===========================================================================
// split fp32 -> (hi, lo) bf16 pairs, packed as bf16x2 words
// returns {h01, h23, l01, l23}; low half of each word = even element
// ===========================================================================
__device__ __forceinline__ uint4 split4(float4 v) {
    uint32_t h01, h23;
    asm("cvt.rn.bf16x2.f32 %0, %1, %2;" : "=r"(h01) : "f"(v.y), "f"(v.x));
    asm("cvt.rn.bf16x2.f32 %0, %1, %2;" : "=r"(h23) : "f"(v.w), "f"(v.z));
    float h0 = __uint_as_float(h01 << 16);
    float h1 = __uint_as_float(h01 & 0xFFFF0000u);
    float h2 = __uint_as_float(h23 << 16);
    float h3 = __uint_as_float(h23 & 0xFFFF0000u);
    uint32_t l01, l23;
    asm("cvt.rn.bf16x2.f32 %0, %1, %2;" : "=r"(l01) : "f"(v.y - h1), "f"(v.x - h0));
    asm("cvt.rn.bf16x2.f32 %0, %1, %2;" : "=r"(l23) : "f"(v.w - h3), "f"(v.z - h2));
    return make_uint4(h01, h23, l01, l23);
}

__device__ __forceinline__ void mma16816(float* c,
                                         uint32_t a0, uint32_t a1, uint32_t a2, uint32_t a3,
                                         uint32_t b0, uint32_t b1) {
    asm volatile(
        "mma.sync.aligned.m16n8k16.row.col.f32.bf16.bf16.f32 "
        "{%0,%1,%2,%3}, {%4,%5,%6,%7}, {%8,%9}, {%0,%1,%2,%3};"
        : "+f"(c[0]), "+f"(c[1]), "+f"(c[2]), "+f"(c[3])
        : "r"(a0), "r"(a1), "r"(a2), "r"(a3), "r"(b0), "r"(b1));
}

// ===========================================================================
// mma.sync split-bf16 GEMM:  C[M,N] = A[M,K] @ B[N,K]^T,  K = 1024, lda=ldb=1024
// CTA 128x128, 8 warps (2x4) of 64x32 warp tiles, BK = 32, double-buffered.
// SMEM per buffer (32KB):
//   A_hi [0,8K):   8 mb x 2 kb blocks of 512B; slot(lane)=16B = frag a-regs
//   A_lo [8K,16K)
//   B    [16K,32K): 16 nb x 2 kb blocks of 512B; slot = {bhi0,bhi1,blo0,blo1}
// Slot index permuted p(s) = s ^ (s>>3) to cap STS bank conflicts at 2-way.
// ===========================================================================
#define TCB_SMEM 65536

__global__ __launch_bounds__(256, 1)
void tc_gemm_kernel(const float* __restrict__ A, const float* __restrict__ B,
                    float* __restrict__ C, int ldc)
{
    extern __shared__ char sm[];
    const int tid  = threadIdx.x;
    const int lane = tid & 31;
    const int wid  = tid >> 5;
    const int wm   = (wid >> 2) * 64;           // warp row offset (0, 64)
    const int wn   = (wid & 3) * 32;            // warp col offset
    const int m0 = blockIdx.y * 128;
    const int n0 = blockIdx.x * 128;
    const int pl = lane ^ (lane >> 3);          // consumer slot permutation

    float acc[4][4][4];
#pragma unroll
    for (int i = 0; i < 4; i++)
#pragma unroll
        for (int j = 0; j < 4; j++)
#pragma unroll
            for (int q = 0; q < 4; q++) acc[i][j][q] = 0.f;

    float4 ra[4], rb[4];

    // ---------------- helpers as macros ----------------
#define LDG_CHUNK(k0)                                                          \
    {                                                                          \
        _Pragma("unroll")                                                      \
        for (int i = 0; i < 4; i++) {                                          \
            int idx = i * 256 + tid;                                           \
            int r = idx >> 3, c4 = (idx & 7) << 2;                             \
            ra[i] = *reinterpret_cast<const float4*>(                          \
                &A[(size_t)(m0 + r) * 1024 + (k0) + c4]);                      \
            rb[i] = *reinterpret_cast<const float4*>(                          \
                &B[(size_t)(n0 + r) * 1024 + (k0) + c4]);                      \
        }                                                                      \
    }

#define STS_CHUNK(bufp)                                                        \
    {                                                                          \
        char* _buf = (bufp);                                                   \
        _Pragma("unroll")                                                      \
        for (int i = 0; i < 4; i++) {                                          \
            int idx = i * 256 + tid;                                           \
            int r = idx >> 3, c4 = (idx & 7) << 2;                             \
            int kb = c4 >> 4, kk = c4 & 15;                                    \
            /* A */                                                            \
            int rr = r & 15, mb = r >> 4;                                      \
            int s  = ((rr & 7) << 2) + ((kk & 7) >> 1);                        \
            int ps  = s ^ (s >> 3);                                            \
            int ps1 = (s + 1) ^ ((s + 1) >> 3);                                \
            int rg = (kk >> 3) + ((rr >> 3) << 1);                             \
            uint4 sp = split4(ra[i]);                                          \
            char* ab = _buf + (((mb << 1) + kb) << 9) + (rg << 2);             \
            *(uint32_t*)(ab + ps  * 16)        = sp.x;                         \
            *(uint32_t*)(ab + ps1 * 16)        = sp.y;                         \
            *(uint32_t*)(ab + 8192 + ps  * 16) = sp.z;                         \
            *(uint32_t*)(ab + 8192 + ps1 * 16) = sp.w;                         \
            /* B */                                                            \
            int nn = r & 7, nb = r >> 3;                                       \
            int sb  = (nn << 2) + ((kk & 7) >> 1);                             \
            int psb  = sb ^ (sb >> 3);                                         \
            int psb1 = (sb + 1) ^ ((sb + 1) >> 3);                             \
            int rgb = kk >> 3;                                                 \
            uint4 sq = split4(rb[i]);                                          \
            char* bb = _buf + 16384 + (((nb << 1) + kb) << 9) + (rgb << 2);    \
            *(uint32_t*)(bb + psb  * 16)     = sq.x;                           \
            *(uint32_t*)(bb + psb1 * 16)     = sq.y;                           \
            *(uint32_t*)(bb + psb  * 16 + 8) = sq.z;                           \
            *(uint32_t*)(bb + psb1 * 16 + 8) = sq.w;                           \
        }                                                                      \
    }

#define COMPUTE_CHUNK(bufp)                                                    \
    {                                                                          \
        const char* _buf = (bufp);                                             \
        _Pragma("unroll")                                                      \
        for (int kb = 0; kb < 2; kb++) {                                       \
            uint4 ah[4], al[4], bq[4];                                         \
            _Pragma("unroll")                                                  \
            for (int am = 0; am < 4; am++) {                                   \
                const char* p = _buf + (((((wm >> 4) + am) << 1) + kb) << 9)   \
                                + pl * 16;                                     \
                ah[am] = *(const uint4*)p;                                     \
                al[am] = *(const uint4*)(p + 8192);                            \
            }                                                                  \
            _Pragma("unroll")                                                  \
            for (int bn = 0; bn < 4; bn++) {                                   \
                const char* p = _buf + 16384                                   \
                                + (((((wn >> 3) + bn) << 1) + kb) << 9)        \
                                + pl * 16;                                     \
                bq[bn] = *(const uint4*)p;                                     \
            }                                                                  \
            _Pragma("unroll")                                                  \
            for (int am = 0; am < 4; am++)                                     \
                _Pragma("unroll")                                              \
                for (int bn = 0; bn < 4; bn++) {                               \
                    float* c = acc[am][bn];                                    \
                    mma16816(c, ah[am].x, ah[am].z, ah[am].y, ah[am].w,        \
                             bq[bn].x, bq[bn].y);                              \
                    mma16816(c, ah[am].x, ah[am].z, ah[am].y, ah[am].w,        \
                             bq[bn].z, bq[bn].w);                              \
                    mma16816(c, al[am].x, al[am].z, al[am].y, al[am].w,        \
                             bq[bn].x, bq[bn].y);                              \
                }                                                              \
        }                                                                      \
    }
    // ---------------------------------------------------

    // prologue
    LDG_CHUNK(0);
    STS_CHUNK(sm);
    __syncthreads();

    for (int ch = 0; ch < 32; ch++) {
        if (ch < 31) LDG_CHUNK((ch + 1) * 32);
        COMPUTE_CHUNK(sm + (ch & 1) * 32768);
        if (ch < 31) {
            STS_CHUNK(sm + ((ch + 1) & 1) * 32768);
            __syncthreads();
        }
    }

    // epilogue
#pragma unroll
    for (int am = 0; am < 4; am++)
#pragma unroll
        for (int bn = 0; bn < 4; bn++) {
            const float* c = acc[am][bn];
            int row = m0 + wm + am * 16 + (lane >> 2);
            int col = n0 + wn + bn * 8 + ((lane & 3) << 1);
            *reinterpret_cast<float2*>(&C[(size_t)row * ldc + col]) =
                make_float2(c[0], c[1]);
            *reinterpret_cast<float2*>(&C[(size_t)(row + 8) * ldc + col]) =
                make_float2(c[2], c[3]);
        }
}

// ---------------------------------------------------------------------------
// Exact fp32 SGEMM (weight folds): C[M,N] = op(A) @ op(B)
// ---------------------------------------------------------------------------
template <bool TA, bool TB>
__global__ __launch_bounds__(256)
void sgemm_kernel(int M, int N, int K,
                  const float* __restrict__ A, int lda,
                  const float* __restrict__ B, int ldb,
                  float* __restrict__ C, int ldc)
{
    constexpr int BM = 128, BN = 128, BK = 8;
    __shared__ float As[BK][BM];
    __shared__ float Bs[BK][BN];

    const int tid = threadIdx.x;
    const int m0 = blockIdx.y * BM;
    const int n0 = blockIdx.x * BN;
    const int tx = tid & 15;
    const int ty = tid >> 4;

    float acc[8][8];
#pragma unroll
    for (int i = 0; i < 8; i++)
#pragma unroll
        for (int j = 0; j < 8; j++) acc[i][j] = 0.f;

    for (int k0 = 0; k0 < K; k0 += BK) {
        if (!TA) {
            const int row = tid >> 1;
            const int c4  = (tid & 1) * 4;
            float4 v = *reinterpret_cast<const float4*>(
                &A[(size_t)(m0 + row) * lda + k0 + c4]);
            As[c4 + 0][row] = v.x;
            As[c4 + 1][row] = v.y;
            As[c4 + 2][row] = v.z;
            As[c4 + 3][row] = v.w;
        } else {
            const int p  = tid >> 5;
            const int m4 = (tid & 31) * 4;
            float4 v = *reinterpret_cast<const float4*>(
                &A[(size_t)(k0 + p) * lda + m0 + m4]);
            *reinterpret_cast<float4*>(&As[p][m4]) = v;
        }
        if (!TB) {
            const int p  = tid >> 5;
            const int n4 = (tid & 31) * 4;
            float4 v = *reinterpret_cast<const float4*>(
                &B[(size_t)(k0 + p) * ldb + n0 + n4]);
            *reinterpret_cast<float4*>(&Bs[p][n4]) = v;
        } else {
            const int row = tid >> 1;
            const int c4  = (tid & 1) * 4;
            float4 v = *reinterpret_cast<const float4*>(
                &B[(size_t)(n0 + row) * ldb + k0 + c4]);
            Bs[c4 + 0][row] = v.x;
            Bs[c4 + 1][row] = v.y;
            Bs[c4 + 2][row] = v.z;
            Bs[c4 + 3][row] = v.w;
        }
        __syncthreads();

#pragma unroll
        for (int p = 0; p < BK; p++) {
            float ar[8], br[8];
            *reinterpret_cast<float4*>(&ar[0]) =
                *reinterpret_cast<const float4*>(&As[p][ty * 8]);
            *reinterpret_cast<float4*>(&ar[4]) =
                *reinterpret_cast<const float4*>(&As[p][ty * 8 + 4]);
            *reinterpret_cast<float4*>(&br[0]) =
                *reinterpret_cast<const float4*>(&Bs[p][tx * 8]);
            *reinterpret_cast<float4*>(&br[4]) =
                *reinterpret_cast<const float4*>(&Bs[p][tx * 8 + 4]);
#pragma unroll
            for (int i = 0; i < 8; i++)
#pragma unroll
                for (int j = 0; j < 8; j++)
                    acc[i][j] = fmaf(ar[i], br[j], acc[i][j]);
        }
        __syncthreads();
    }

#pragma unroll
    for (int i = 0; i < 8; i++) {
        float* cp = &C[(size_t)(m0 + ty * 8 + i) * ldc + n0 + tx * 8];
        *reinterpret_cast<float4*>(cp) =
            make_float4(acc[i][0], acc[i][1], acc[i][2], acc[i][3]);
        *reinterpret_cast<float4*>(cp + 4) =
            make_float4(acc[i][4], acc[i][5], acc[i][6], acc[i][7]);
    }
}

// ---------------------------------------------------------------------------
// Flash-style attention (fp32, per-thread row). QKV fused layout, stride 3072.
// ---------------------------------------------------------------------------
#define QT 128
#define KT 32

__global__ __launch_bounds__(QT)
void flash_attn_kernel(const float* __restrict__ QKV,
                       const float* __restrict__ entangle,
                       float* __restrict__ O)
{
    const int b = blockIdx.z;
    const int h = blockIdx.y;
    const int q0 = blockIdx.x * QT;
    const int row = threadIdx.x;

    const float scale = entangle[h] * 0.125f;

    const size_t m = (size_t)b * LL + q0 + row;
    const float* qptr = QKV + m * QKV_LD + h * HD;

    float q[HD];
#pragma unroll
    for (int d = 0; d < HD; d++) q[d] = qptr[d] * scale;

    float acc[HD];
#pragma unroll
    for (int d = 0; d < HD; d++) acc[d] = 0.f;
    float mi = -INFINITY;
    float li = 0.f;

    __shared__ float Ks[KT][HD];
    __shared__ float Vs[KT][HD];

    const float* Kp = QKV + (size_t)DD     + ((size_t)b * LL) * QKV_LD + h * HD;
    const float* Vp = QKV + (size_t)2 * DD + ((size_t)b * LL) * QKV_LD + h * HD;

    for (int k0 = 0; k0 < LL; k0 += KT) {
        __syncthreads();
#pragma unroll
        for (int it = 0; it < (KT * HD / 4) / QT; it++) {
            int idx = threadIdx.x + it * QT;
            int j = idx >> 4;
            int c = idx & 15;
            *reinterpret_cast<float4*>(&Ks[j][c * 4]) =
                *reinterpret_cast<const float4*>(&Kp[(size_t)(k0 + j) * QKV_LD + c * 4]);
            *reinterpret_cast<float4*>(&Vs[j][c * 4]) =
                *reinterpret_cast<const float4*>(&Vp[(size_t)(k0 + j) * QKV_LD + c * 4]);
        }
        __syncthreads();

        float s[KT];
        float mnew = mi;
#pragma unroll
        for (int j = 0; j < KT; j++) {
            const float4* k4 = reinterpret_cast<const float4*>(&Ks[j][0]);
            float sum = 0.f;
#pragma unroll
            for (int c = 0; c < HD / 4; c++) {
                float4 kv = k4[c];
                sum = fmaf(q[4 * c + 0], kv.x, sum);
                sum = fmaf(q[4 * c + 1], kv.y, sum);
                sum = fmaf(q[4 * c + 2], kv.z, sum);
                sum = fmaf(q[4 * c + 3], kv.w, sum);
            }
            s[j] = sum;
            mnew = fmaxf(mnew, sum);
        }

        if (mnew > mi) {
            float corr = __expf(mi - mnew);
            li *= corr;
#pragma unroll
            for (int d = 0; d < HD; d++) acc[d] *= corr;
            mi = mnew;
        }

#pragma unroll
        for (int j = 0; j < KT; j++) {
            float p = __expf(s[j] - mi);
            li += p;
            const float4* v4 = reinterpret_cast<const float4*>(&Vs[j][0]);
#pragma unroll
            for (int c = 0; c < HD / 4; c++) {
                float4 vv = v4[c];
                acc[4 * c + 0] = fmaf(p, vv.x, acc[4 * c + 0]);
                acc[4 * c + 1] = fmaf(p, vv.y, acc[4 * c + 1]);
                acc[4 * c + 2] = fmaf(p, vv.z, acc[4 * c + 2]);
                acc[4 * c + 3] = fmaf(p, vv.w, acc[4 * c + 3]);
            }
        }
    }

    const float inv = 1.f / li;
    float* optr = O + m * DD + h * HD;
#pragma unroll
    for (int c = 0; c < HD / 4; c++) {
        *reinterpret_cast<float4*>(&optr[4 * c]) =
            make_float4(acc[4 * c + 0] * inv, acc[4 * c + 1] * inv,
                        acc[4 * c + 2] * inv, acc[4 * c + 3] * inv);
    }
}

// ---------------------------------------------------------------------------
// Launch
// ---------------------------------------------------------------------------
extern "C" void kernel_launch(void* const* d_in, const int* in_sizes, int n_in,
                              void* d_out, int out_size)
{
    const float* X   = (const float*)d_in[0];   // (B, L, D)
    const float* R   = (const float*)d_in[1];   // (D, D)
    const float* ent = (const float*)d_in[2];   // (H,)
    const float* Wq  = (const float*)d_in[3];
    const float* Wk  = (const float*)d_in[4];
    const float* Wv  = (const float*)d_in[5];
    const float* Wo  = (const float*)d_in[6];
    float* out = (float*)d_out;

    float *wfoldT, *qkv, *ao;
    cudaGetSymbolAddress((void**)&wfoldT, g_WfoldT);
    cudaGetSymbolAddress((void**)&qkv,    g_QKV);
    cudaGetSymbolAddress((void**)&ao,     g_AO);

    static int smem_set = 0;
    if (!smem_set) {
        cudaFuncSetAttribute(tc_gemm_kernel,
                             cudaFuncAttributeMaxDynamicSharedMemorySize, TCB_SMEM);
        smem_set = 1;
    }

    dim3 blk(256);
    dim3 gridW(DD / 128, DD / 128);

    // 1) Fold weights: WfoldT_i = R^T @ W_i  (exact fp32)
    const float* W[3] = {Wq, Wk, Wv};
    for (int i = 0; i < 3; i++) {
        sgemm_kernel<true, false><<<gridW, blk>>>(
            DD, DD, DD, R, DD, W[i], DD, wfoldT + (size_t)i * DD * DD, DD);
    }

    // 2) Fused QKV projection on tensor cores (split-bf16, 3-pass):
    //    QKV[M, 3072] = X[M,1024] @ WfoldT[3072,1024]^T
    {
        dim3 g(3 * DD / 128, MM / 128);   // (24, 32)
        tc_gemm_kernel<<<g, 256, TCB_SMEM>>>(X, wfoldT, qkv, QKV_LD);
    }

    // 3) Attention
    {
        dim3 gridA(LL / QT, HH, BB);
        flash_attn_kernel<<<gridA, QT>>>(qkv, ent, ao);
    }

    // 4) Output projection on tensor cores: out = AO @ Wo^T
    {
        dim3 g(DD / 128, MM / 128);       // (8, 32)
        tc_gemm_kernel<<<g, 256, TCB_SMEM>>>(ao, Wo, out, DD);
    }
}

// round 4
// speedup vs baseline: 2.6451x; 2.3909x over previous
#include <cuda_runtime.h>
#include <cuda_bf16.h>
#include <math.h>
#include <stdint.h>

// Problem constants
#define BB   2
#define LL   2048
#define DD   1024
#define HH   16
#define HD   64
#define MM   (BB*LL)          // 4096
#define QKV_LD (3*DD)         // fused QKV row stride

// Scratch (static device memory -- no allocations allowed)
__device__ float g_WfoldT[3 * DD * DD];   // R^T @ W_i  ([n][k] B-operand layout)
__device__ float g_QKV[MM * 3 * DD];      // fused [M][3072]: Q | K | V
__device__ float g_AO[MM * DD];           // attention output (M x D)

// ===========================================================================
// helpers
// ===========================================================================
__device__ __forceinline__ uint4 split4(float4 v) {
    uint32_t h01, h23;
    asm("cvt.rn.bf16x2.f32 %0, %1, %2;" : "=r"(h01) : "f"(v.y), "f"(v.x));
    asm("cvt.rn.bf16x2.f32 %0, %1, %2;" : "=r"(h23) : "f"(v.w), "f"(v.z));
    float h0 = __uint_as_float(h01 << 16);
    float h1 = __uint_as_float(h01 & 0xFFFF0000u);
    float h2 = __uint_as_float(h23 << 16);
    float h3 = __uint_as_float(h23 & 0xFFFF0000u);
    uint32_t l01, l23;
    asm("cvt.rn.bf16x2.f32 %0, %1, %2;" : "=r"(l01) : "f"(v.y - h1), "f"(v.x - h0));
    asm("cvt.rn.bf16x2.f32 %0, %1, %2;" : "=r"(l23) : "f"(v.w - h3), "f"(v.z - h2));
    return make_uint4(h01, h23, l01, l23);
}

// bf16 mma (used by the projection GEMMs)
__device__ __forceinline__ void mma16816(float* c,
                                         uint32_t a0, uint32_t a1, uint32_t a2, uint32_t a3,
                                         uint32_t b0, uint32_t b1) {
    asm volatile(
        "mma.sync.aligned.m16n8k16.row.col.f32.bf16.bf16.f32 "
        "{%0,%1,%2,%3}, {%4,%5,%6,%7}, {%8,%9}, {%0,%1,%2,%3};"
        : "+f"(c[0]), "+f"(c[1]), "+f"(c[2]), "+f"(c[3])
        : "r"(a0), "r"(a1), "r"(a2), "r"(a3), "r"(b0), "r"(b1));
}

// fp16 mma (attention)
__device__ __forceinline__ void mma16816h(float* c,
                                          uint32_t a0, uint32_t a1, uint32_t a2, uint32_t a3,
                                          uint32_t b0, uint32_t b1) {
    asm volatile(
        "mma.sync.aligned.m16n8k16.row.col.f32.f16.f16.f32 "
        "{%0,%1,%2,%3}, {%4,%5,%6,%7}, {%8,%9}, {%0,%1,%2,%3};"
        : "+f"(c[0]), "+f"(c[1]), "+f"(c[2]), "+f"(c[3])
        : "r"(a0), "r"(a1), "r"(a2), "r"(a3), "r"(b0), "r"(b1));
}

// pack two fp32 -> f16x2 (lo in low half)
__device__ __forceinline__ uint32_t pkf16(float lo, float hi) {
    uint32_t r;
    asm("cvt.rn.f16x2.f32 %0, %1, %2;" : "=r"(r) : "f"(hi), "f"(lo));
    return r;
}

__device__ __forceinline__ float ex2(float x) {
    float r;
    asm("ex2.approx.f32 %0, %1;" : "=f"(r) : "f"(x));
    return r;
}

// ===========================================================================
// mma.sync split-bf16 GEMM:  C[M,N] = A[M,K] @ B[N,K]^T,  K = 1024
// (unchanged from round 3 — 48% tensor pipe)
// ===========================================================================
#define TCB_SMEM 65536

__global__ __launch_bounds__(256, 1)
void tc_gemm_kernel(const float* __restrict__ A, const float* __restrict__ B,
                    float* __restrict__ C, int ldc)
{
    extern __shared__ char sm[];
    const int tid  = threadIdx.x;
    const int lane = tid & 31;
    const int wid  = tid >> 5;
    const int wm   = (wid >> 2) * 64;
    const int wn   = (wid & 3) * 32;
    const int m0 = blockIdx.y * 128;
    const int n0 = blockIdx.x * 128;
    const int pl = lane ^ (lane >> 3);

    float acc[4][4][4];
#pragma unroll
    for (int i = 0; i < 4; i++)
#pragma unroll
        for (int j = 0; j < 4; j++)
#pragma unroll
            for (int q = 0; q < 4; q++) acc[i][j][q] = 0.f;

    float4 ra[4], rb[4];

#define LDG_CHUNK(k0)                                                          \
    {                                                                          \
        _Pragma("unroll")                                                      \
        for (int i = 0; i < 4; i++) {                                          \
            int idx = i * 256 + tid;                                           \
            int r = idx >> 3, c4 = (idx & 7) << 2;                             \
            ra[i] = *reinterpret_cast<const float4*>(                          \
                &A[(size_t)(m0 + r) * 1024 + (k0) + c4]);                      \
            rb[i] = *reinterpret_cast<const float4*>(                          \
                &B[(size_t)(n0 + r) * 1024 + (k0) + c4]);                      \
        }                                                                      \
    }

#define STS_CHUNK(bufp)                                                        \
    {                                                                          \
        char* _buf = (bufp);                                                   \
        _Pragma("unroll")                                                      \
        for (int i = 0; i < 4; i++) {                                          \
            int idx = i * 256 + tid;                                           \
            int r = idx >> 3, c4 = (idx & 7) << 2;                             \
            int kb = c4 >> 4, kk = c4 & 15;                                    \
            int rr = r & 15, mb = r >> 4;                                      \
            int s  = ((rr & 7) << 2) + ((kk & 7) >> 1);                        \
            int ps  = s ^ (s >> 3);                                            \
            int ps1 = (s + 1) ^ ((s + 1) >> 3);                                \
            int rg = (kk >> 3) + ((rr >> 3) << 1);                             \
            uint4 sp = split4(ra[i]);                                          \
            char* ab = _buf + (((mb << 1) + kb) << 9) + (rg << 2);             \
            *(uint32_t*)(ab + ps  * 16)        = sp.x;                         \
            *(uint32_t*)(ab + ps1 * 16)        = sp.y;                         \
            *(uint32_t*)(ab + 8192 + ps  * 16) = sp.z;                         \
            *(uint32_t*)(ab + 8192 + ps1 * 16) = sp.w;                         \
            int nn = r & 7, nb = r >> 3;                                       \
            int sb  = (nn << 2) + ((kk & 7) >> 1);                             \
            int psb  = sb ^ (sb >> 3);                                         \
            int psb1 = (sb + 1) ^ ((sb + 1) >> 3);                             \
            int rgb = kk >> 3;                                                 \
            uint4 sq = split4(rb[i]);                                          \
            char* bb = _buf + 16384 + (((nb << 1) + kb) << 9) + (rgb << 2);    \
            *(uint32_t*)(bb + psb  * 16)     = sq.x;                           \
            *(uint32_t*)(bb + psb1 * 16)     = sq.y;                           \
            *(uint32_t*)(bb + psb  * 16 + 8) = sq.z;                           \
            *(uint32_t*)(bb + psb1 * 16 + 8) = sq.w;                           \
        }                                                                      \
    }

#define COMPUTE_CHUNK(bufp)                                                    \
    {                                                                          \
        const char* _buf = (bufp);                                             \
        _Pragma("unroll")                                                      \
        for (int kb = 0; kb < 2; kb++) {                                       \
            uint4 ah[4], al[4], bq[4];                                         \
            _Pragma("unroll")                                                  \
            for (int am = 0; am < 4; am++) {                                   \
                const char* p = _buf + (((((wm >> 4) + am) << 1) + kb) << 9)   \
                                + pl * 16;                                     \
                ah[am] = *(const uint4*)p;                                     \
                al[am] = *(const uint4*)(p + 8192);                            \
            }                                                                  \
            _Pragma("unroll")                                                  \
            for (int bn = 0; bn < 4; bn++) {                                   \
                const char* p = _buf + 16384                                   \
                                + (((((wn >> 3) + bn) << 1) + kb) << 9)        \
                                + pl * 16;                                     \
                bq[bn] = *(const uint4*)p;                                     \
            }                                                                  \
            _Pragma("unroll")                                                  \
            for (int am = 0; am < 4; am++)                                     \
                _Pragma("unroll")                                              \
                for (int bn = 0; bn < 4; bn++) {                               \
                    float* c = acc[am][bn];                                    \
                    mma16816(c, ah[am].x, ah[am].z, ah[am].y, ah[am].w,        \
                             bq[bn].x, bq[bn].y);                              \
                    mma16816(c, ah[am].x, ah[am].z, ah[am].y, ah[am].w,        \
                             bq[bn].z, bq[bn].w);                              \
                    mma16816(c, al[am].x, al[am].z, al[am].y, al[am].w,        \
                             bq[bn].x, bq[bn].y);                              \
                }                                                              \
        }                                                                      \
    }

    LDG_CHUNK(0);
    STS_CHUNK(sm);
    __syncthreads();

    for (int ch = 0; ch < 32; ch++) {
        if (ch < 31) LDG_CHUNK((ch + 1) * 32);
        COMPUTE_CHUNK(sm + (ch & 1) * 32768);
        if (ch < 31) {
            STS_CHUNK(sm + ((ch + 1) & 1) * 32768);
            __syncthreads();
        }
    }

#pragma unroll
    for (int am = 0; am < 4; am++)
#pragma unroll
        for (int bn = 0; bn < 4; bn++) {
            const float* c = acc[am][bn];
            int row = m0 + wm + am * 16 + (lane >> 2);
            int col = n0 + wn + bn * 8 + ((lane & 3) << 1);
            *reinterpret_cast<float2*>(&C[(size_t)row * ldc + col]) =
                make_float2(c[0], c[1]);
            *reinterpret_cast<float2*>(&C[(size_t)(row + 8) * ldc + col]) =
                make_float2(c[2], c[3]);
        }
#undef LDG_CHUNK
#undef STS_CHUNK
#undef COMPUTE_CHUNK
}

// ---------------------------------------------------------------------------
// Exact fp32 SGEMM (weight folds): C[M,N] = op(A) @ op(B)
// ---------------------------------------------------------------------------
template <bool TA, bool TB>
__global__ __launch_bounds__(256)
void sgemm_kernel(int M, int N, int K,
                  const float* __restrict__ A, int lda,
                  const float* __restrict__ B, int ldb,
                  float* __restrict__ C, int ldc)
{
    constexpr int BM = 128, BN = 128, BK = 8;
    __shared__ float As[BK][BM];
    __shared__ float Bs[BK][BN];

    const int tid = threadIdx.x;
    const int m0 = blockIdx.y * BM;
    const int n0 = blockIdx.x * BN;
    const int tx = tid & 15;
    const int ty = tid >> 4;

    float acc[8][8];
#pragma unroll
    for (int i = 0; i < 8; i++)
#pragma unroll
        for (int j = 0; j < 8; j++) acc[i][j] = 0.f;

    for (int k0 = 0; k0 < K; k0 += BK) {
        if (!TA) {
            const int row = tid >> 1;
            const int c4  = (tid & 1) * 4;
            float4 v = *reinterpret_cast<const float4*>(
                &A[(size_t)(m0 + row) * lda + k0 + c4]);
            As[c4 + 0][row] = v.x; As[c4 + 1][row] = v.y;
            As[c4 + 2][row] = v.z; As[c4 + 3][row] = v.w;
        } else {
            const int p  = tid >> 5;
            const int m4 = (tid & 31) * 4;
            float4 v = *reinterpret_cast<const float4*>(
                &A[(size_t)(k0 + p) * lda + m0 + m4]);
            *reinterpret_cast<float4*>(&As[p][m4]) = v;
        }
        if (!TB) {
            const int p  = tid >> 5;
            const int n4 = (tid & 31) * 4;
            float4 v = *reinterpret_cast<const float4*>(
                &B[(size_t)(k0 + p) * ldb + n0 + n4]);
            *reinterpret_cast<float4*>(&Bs[p][n4]) = v;
        } else {
            const int row = tid >> 1;
            const int c4  = (tid & 1) * 4;
            float4 v = *reinterpret_cast<const float4*>(
                &B[(size_t)(n0 + row) * ldb + k0 + c4]);
            Bs[c4 + 0][row] = v.x; Bs[c4 + 1][row] = v.y;
            Bs[c4 + 2][row] = v.z; Bs[c4 + 3][row] = v.w;
        }
        __syncthreads();

#pragma unroll
        for (int p = 0; p < BK; p++) {
            float ar[8], br[8];
            *reinterpret_cast<float4*>(&ar[0]) =
                *reinterpret_cast<const float4*>(&As[p][ty * 8]);
            *reinterpret_cast<float4*>(&ar[4]) =
                *reinterpret_cast<const float4*>(&As[p][ty * 8 + 4]);
            *reinterpret_cast<float4*>(&br[0]) =
                *reinterpret_cast<const float4*>(&Bs[p][tx * 8]);
            *reinterpret_cast<float4*>(&br[4]) =
                *reinterpret_cast<const float4*>(&Bs[p][tx * 8 + 4]);
#pragma unroll
            for (int i = 0; i < 8; i++)
#pragma unroll
                for (int j = 0; j < 8; j++)
                    acc[i][j] = fmaf(ar[i], br[j], acc[i][j]);
        }
        __syncthreads();
    }

#pragma unroll
    for (int i = 0; i < 8; i++) {
        float* cp = &C[(size_t)(m0 + ty * 8 + i) * ldc + n0 + tx * 8];
        *reinterpret_cast<float4*>(cp) =
            make_float4(acc[i][0], acc[i][1], acc[i][2], acc[i][3]);
        *reinterpret_cast<float4*>(cp + 4) =
            make_float4(acc[i][4], acc[i][5], acc[i][6], acc[i][7]);
    }
}

// ===========================================================================
// Tensor-core flash attention (fp16 mma, fp32 softmax/accum).
// Grid (16 qtiles, 16 heads, 2 batch), 256 threads = 8 warps x m16 rows.
// 64-key chunks, double-buffered; K/V stored in SMEM pre-shuffled as
// m16n8k16 B-fragment blocks (264B stride, XOR slot permutation).
//   QK: B(k=dim, n=key)  -> blocks (nb=key>>3, kb=dim>>4)
//   PV: B(k=key, n=dim)  -> blocks (nb=dim>>3, kb=key>>4)
// ===========================================================================
#define FA_BUFSZ 16896          // (8448 K + 8448 V) per buffer

__global__ __launch_bounds__(256)
void flash_attn_tc(const float* __restrict__ QKV,
                   const float* __restrict__ entangle,
                   float* __restrict__ O)
{
    __shared__ char sm_[2 * FA_BUFSZ];

    const int b  = blockIdx.z;
    const int h  = blockIdx.y;
    const int qt = blockIdx.x;
    const int tid  = threadIdx.x;
    const int lane = tid & 31;
    const int wid  = tid >> 5;
    const int t = lane & 3;
    const int r = lane >> 2;
    const int pl = lane ^ (lane >> 3);

    const float scale = entangle[h] * 0.125f * 1.44269504f;  // fold log2(e)

    // ---- Q fragments (once) ----
    const int mrow = b * LL + qt * 128 + wid * 16 + r;
    const float* q0p = QKV + (size_t)mrow * QKV_LD + h * HD;
    const float* q8p = q0p + (size_t)8 * QKV_LD;
    uint32_t qa[4][4];
#pragma unroll
    for (int kb = 0; kb < 4; kb++) {
        const int c = kb * 16 + 2 * t;
        float2 v0a = *reinterpret_cast<const float2*>(q0p + c);
        float2 v8a = *reinterpret_cast<const float2*>(q8p + c);
        float2 v0b = *reinterpret_cast<const float2*>(q0p + c + 8);
        float2 v8b = *reinterpret_cast<const float2*>(q8p + c + 8);
        qa[kb][0] = pkf16(v0a.x * scale, v0a.y * scale);
        qa[kb][1] = pkf16(v8a.x * scale, v8a.y * scale);
        qa[kb][2] = pkf16(v0b.x * scale, v0b.y * scale);
        qa[kb][3] = pkf16(v8b.x * scale, v8b.y * scale);
    }

    float oc[8][4];
#pragma unroll
    for (int i = 0; i < 8; i++)
#pragma unroll
        for (int j = 0; j < 4; j++) oc[i][j] = 0.f;
    float l0 = 0.f, l1 = 0.f;
    float mx0 = -1e30f, mx1 = -1e30f;

    const float* Kg = QKV + (size_t)DD     + ((size_t)b * LL) * QKV_LD + h * HD;
    const float* Vg = QKV + (size_t)2 * DD + ((size_t)b * LL) * QKV_LD + h * HD;

    float kstf[4][4];   // K staging: 4 float4
    float vstf[4][4];   // V staging: 2 key-pair units x 2 float4

#define FA_LDG(ch)                                                             \
    {                                                                          \
        _Pragma("unroll")                                                      \
        for (int i = 0; i < 4; i++) {                                          \
            int idx = i * 256 + tid;                                           \
            int key = idx >> 4, c4 = (idx & 15) << 2;                          \
            *reinterpret_cast<float4*>(kstf[i]) =                              \
                *reinterpret_cast<const float4*>(                              \
                    &Kg[(size_t)((ch) * 64 + key) * QKV_LD + c4]);             \
        }                                                                      \
        _Pragma("unroll")                                                      \
        for (int j = 0; j < 2; j++) {                                          \
            int u = j * 256 + tid;                                             \
            int keyA = (u >> 4) * 2, c4 = (u & 15) << 2;                       \
            *reinterpret_cast<float4*>(vstf[2 * j]) =                          \
                *reinterpret_cast<const float4*>(                              \
                    &Vg[(size_t)((ch) * 64 + keyA) * QKV_LD + c4]);            \
            *reinterpret_cast<float4*>(vstf[2 * j + 1]) =                      \
                *reinterpret_cast<const float4*>(                              \
                    &Vg[(size_t)((ch) * 64 + keyA + 1) * QKV_LD + c4]);        \
        }                                                                      \
    }

#define FA_STS(bufp)                                                           \
    {                                                                          \
        char* _kb_ = (bufp);                                                   \
        char* _vb_ = (bufp) + 8448;                                            \
        _Pragma("unroll")                                                      \
        for (int i = 0; i < 4; i++) {                                          \
            int idx = i * 256 + tid;                                           \
            int key = idx >> 4, d = (idx & 15) << 2;                           \
            int nb = key >> 3, kb = d >> 4;                                    \
            int w = (d >> 3) & 1;                                              \
            int L  = ((key & 7) << 2) | ((d >> 1) & 3);                        \
            int L2 = L + 1;                                                    \
            int pL  = L ^ (L >> 3);                                            \
            int pL2 = L2 ^ (L2 >> 3);                                          \
            char* base = _kb_ + ((nb << 2) | kb) * 264;                        \
            *(uint32_t*)(base + pL  * 8 + w * 4) = pkf16(kstf[i][0], kstf[i][1]); \
            *(uint32_t*)(base + pL2 * 8 + w * 4) = pkf16(kstf[i][2], kstf[i][3]); \
        }                                                                      \
        _Pragma("unroll")                                                      \
        for (int j = 0; j < 2; j++) {                                          \
            int u = j * 256 + tid;                                             \
            int keyA = (u >> 4) * 2, d = (u & 15) << 2;                        \
            int kb = keyA >> 4;                                                \
            int w = (keyA >> 3) & 1;                                           \
            _Pragma("unroll")                                                  \
            for (int i2 = 0; i2 < 4; i2++) {                                   \
                int dim = d + i2;                                              \
                int nb = dim >> 3;                                             \
                int L = ((dim & 7) << 2) | ((keyA >> 1) & 3);                  \
                int pL = L ^ (L >> 3);                                         \
                *(uint32_t*)(_vb_ + ((nb << 2) | kb) * 264 + pL * 8 + w * 4) = \
                    pkf16(vstf[2 * j][i2], vstf[2 * j + 1][i2]);               \
            }                                                                  \
        }                                                                      \
    }

#define FA_COMPUTE(bufp)                                                       \
    {                                                                          \
        const char* _kb_ = (bufp);                                             \
        const char* _vb_ = (bufp) + 8448;                                      \
        float sc[8][4];                                                        \
        _Pragma("unroll")                                                      \
        for (int nb = 0; nb < 8; nb++) {                                       \
            sc[nb][0] = sc[nb][1] = sc[nb][2] = sc[nb][3] = 0.f;               \
            _Pragma("unroll")                                                  \
            for (int kb = 0; kb < 4; kb++) {                                   \
                uint2 bb = *(const uint2*)(_kb_ + ((nb << 2) | kb) * 264       \
                                           + pl * 8);                          \
                mma16816h(sc[nb], qa[kb][0], qa[kb][1], qa[kb][2], qa[kb][3],  \
                          bb.x, bb.y);                                         \
            }                                                                  \
        }                                                                      \
        /* online softmax (log2 domain) */                                     \
        float cm0 = mx0, cm1 = mx1;                                            \
        _Pragma("unroll")                                                      \
        for (int nb = 0; nb < 8; nb++) {                                       \
            cm0 = fmaxf(cm0, fmaxf(sc[nb][0], sc[nb][1]));                     \
            cm1 = fmaxf(cm1, fmaxf(sc[nb][2], sc[nb][3]));                     \
        }                                                                      \
        cm0 = fmaxf(cm0, __shfl_xor_sync(0xffffffffu, cm0, 1));                \
        cm0 = fmaxf(cm0, __shfl_xor_sync(0xffffffffu, cm0, 2));                \
        cm1 = fmaxf(cm1, __shfl_xor_sync(0xffffffffu, cm1, 1));                \
        cm1 = fmaxf(cm1, __shfl_xor_sync(0xffffffffu, cm1, 2));                \
        float corr0 = ex2(mx0 - cm0), corr1 = ex2(mx1 - cm1);                  \
        mx0 = cm0; mx1 = cm1;                                                  \
        float sum0 = 0.f, sum1 = 0.f;                                          \
        _Pragma("unroll")                                                      \
        for (int nb = 0; nb < 8; nb++) {                                       \
            sc[nb][0] = ex2(sc[nb][0] - mx0); sum0 += sc[nb][0];               \
            sc[nb][1] = ex2(sc[nb][1] - mx0); sum0 += sc[nb][1];               \
            sc[nb][2] = ex2(sc[nb][2] - mx1); sum1 += sc[nb][2];               \
            sc[nb][3] = ex2(sc[nb][3] - mx1); sum1 += sc[nb][3];               \
        }                                                                      \
        sum0 += __shfl_xor_sync(0xffffffffu, sum0, 1);                         \
        sum0 += __shfl_xor_sync(0xffffffffu, sum0, 2);                         \
        sum1 += __shfl_xor_sync(0xffffffffu, sum1, 1);                         \
        sum1 += __shfl_xor_sync(0xffffffffu, sum1, 2);                         \
        l0 = l0 * corr0 + sum0;                                                \
        l1 = l1 * corr1 + sum1;                                                \
        _Pragma("unroll")                                                      \
        for (int nb = 0; nb < 8; nb++) {                                       \
            oc[nb][0] *= corr0; oc[nb][1] *= corr0;                            \
            oc[nb][2] *= corr1; oc[nb][3] *= corr1;                            \
        }                                                                      \
        /* P fragments + PV */                                                 \
        _Pragma("unroll")                                                      \
        for (int kt = 0; kt < 4; kt++) {                                       \
            uint32_t pa0 = pkf16(sc[2 * kt][0],     sc[2 * kt][1]);            \
            uint32_t pa1 = pkf16(sc[2 * kt][2],     sc[2 * kt][3]);            \
            uint32_t pa2 = pkf16(sc[2 * kt + 1][0], sc[2 * kt + 1][1]);        \
            uint32_t pa3 = pkf16(sc[2 * kt + 1][2], sc[2 * kt + 1][3]);        \
            _Pragma("unroll")                                                  \
            for (int nb = 0; nb < 8; nb++) {                                   \
                uint2 vv = *(const uint2*)(_vb_ + ((nb << 2) | kt) * 264       \
                                           + pl * 8);                          \
                mma16816h(oc[nb], pa0, pa1, pa2, pa3, vv.x, vv.y);             \
            }                                                                  \
        }                                                                      \
    }

    FA_LDG(0);
    FA_STS(sm_);
    __syncthreads();

    for (int ch = 0; ch < 32; ch++) {
        if (ch < 31) FA_LDG(ch + 1);
        FA_COMPUTE(sm_ + (ch & 1) * FA_BUFSZ);
        if (ch < 31) {
            FA_STS(sm_ + ((ch + 1) & 1) * FA_BUFSZ);
            __syncthreads();
        }
    }

    // ---- epilogue ----
    const float inv0 = 1.f / l0;
    const float inv1 = 1.f / l1;
    float* o0 = O + (size_t)mrow * DD + h * HD;
    float* o8 = o0 + (size_t)8 * DD;
#pragma unroll
    for (int nb = 0; nb < 8; nb++) {
        *reinterpret_cast<float2*>(o0 + nb * 8 + 2 * t) =
            make_float2(oc[nb][0] * inv0, oc[nb][1] * inv0);
        *reinterpret_cast<float2*>(o8 + nb * 8 + 2 * t) =
            make_float2(oc[nb][2] * inv1, oc[nb][3] * inv1);
    }
#undef FA_LDG
#undef FA_STS
#undef FA_COMPUTE
}

// ---------------------------------------------------------------------------
// Launch
// ---------------------------------------------------------------------------
extern "C" void kernel_launch(void* const* d_in, const int* in_sizes, int n_in,
                              void* d_out, int out_size)
{
    const float* X   = (const float*)d_in[0];
    const float* R   = (const float*)d_in[1];
    const float* ent = (const float*)d_in[2];
    const float* Wq  = (const float*)d_in[3];
    const float* Wk  = (const float*)d_in[4];
    const float* Wv  = (const float*)d_in[5];
    const float* Wo  = (const float*)d_in[6];
    float* out = (float*)d_out;

    float *wfoldT, *qkv, *ao;
    cudaGetSymbolAddress((void**)&wfoldT, g_WfoldT);
    cudaGetSymbolAddress((void**)&qkv,    g_QKV);
    cudaGetSymbolAddress((void**)&ao,     g_AO);

    static int smem_set = 0;
    if (!smem_set) {
        cudaFuncSetAttribute(tc_gemm_kernel,
                             cudaFuncAttributeMaxDynamicSharedMemorySize, TCB_SMEM);
        smem_set = 1;
    }

    dim3 blk(256);
    dim3 gridW(DD / 128, DD / 128);

    // 1) Fold weights: WfoldT_i = R^T @ W_i  (exact fp32)
    const float* W[3] = {Wq, Wk, Wv};
    for (int i = 0; i < 3; i++) {
        sgemm_kernel<true, false><<<gridW, blk>>>(
            DD, DD, DD, R, DD, W[i], DD, wfoldT + (size_t)i * DD * DD, DD);
    }

    // 2) Fused QKV projection (split-bf16 tensor cores)
    {
        dim3 g(3 * DD / 128, MM / 128);
        tc_gemm_kernel<<<g, 256, TCB_SMEM>>>(X, wfoldT, qkv, QKV_LD);
    }

    // 3) Tensor-core flash attention
    {
        dim3 gA(LL / 128, HH, BB);
        flash_attn_tc<<<gA, 256>>>(qkv, ent, ao);
    }

    // 4) Output projection (split-bf16 tensor cores)
    {
        dim3 g(DD / 128, MM / 128);
        tc_gemm_kernel<<<g, 256, TCB_SMEM>>>(ao, Wo, out, DD);
    }
}

// round 6
// speedup vs baseline: 4.6548x; 1.7598x over previous
#include <cuda_runtime.h>
#include <cuda_bf16.h>
#include <math.h>
#include <stdint.h>

// Problem constants
#define BB   2
#define LL   2048
#define DD   1024
#define HH   16
#define HD   64
#define MM   (BB*LL)          // 4096
#define QKV_LD (3*DD)         // fused QKV row stride

// Scratch (static device memory -- no allocations allowed)
__device__ float g_WfoldT[3 * DD * DD];   // R^T @ W_i  ([n][k] B-operand layout)
__device__ float g_QKV[MM * 3 * DD];      // fused [M][3072]: Q | K | V
__device__ float g_AO[MM * DD];           // attention output (M x D)
__device__ float g_RT[DD * DD];           // R^T
__device__ float g_WT[3 * DD * DD];       // W_i^T
// fp16 fragment-layout K/V: per (b,h,chunk64) 32 blocks of 256B
__device__ uint32_t g_Kh[BB * HH * 32 * 32 * 64];   // 8MB
__device__ uint32_t g_Vh[BB * HH * 32 * 32 * 64];   // 8MB

// ===========================================================================
// helpers
// ===========================================================================
__device__ __forceinline__ uint4 split4(float4 v) {
    uint32_t h01, h23;
    asm("cvt.rn.bf16x2.f32 %0, %1, %2;" : "=r"(h01) : "f"(v.y), "f"(v.x));
    asm("cvt.rn.bf16x2.f32 %0, %1, %2;" : "=r"(h23) : "f"(v.w), "f"(v.z));
    float h0 = __uint_as_float(h01 << 16);
    float h1 = __uint_as_float(h01 & 0xFFFF0000u);
    float h2 = __uint_as_float(h23 << 16);
    float h3 = __uint_as_float(h23 & 0xFFFF0000u);
    uint32_t l01, l23;
    asm("cvt.rn.bf16x2.f32 %0, %1, %2;" : "=r"(l01) : "f"(v.y - h1), "f"(v.x - h0));
    asm("cvt.rn.bf16x2.f32 %0, %1, %2;" : "=r"(l23) : "f"(v.w - h3), "f"(v.z - h2));
    return make_uint4(h01, h23, l01, l23);
}

__device__ __forceinline__ void mma16816(float* c,
                                         uint32_t a0, uint32_t a1, uint32_t a2, uint32_t a3,
                                         uint32_t b0, uint32_t b1) {
    asm volatile(
        "mma.sync.aligned.m16n8k16.row.col.f32.bf16.bf16.f32 "
        "{%0,%1,%2,%3}, {%4,%5,%6,%7}, {%8,%9}, {%0,%1,%2,%3};"
        : "+f"(c[0]), "+f"(c[1]), "+f"(c[2]), "+f"(c[3])
        : "r"(a0), "r"(a1), "r"(a2), "r"(a3), "r"(b0), "r"(b1));
}

__device__ __forceinline__ void mma16816h(float* c,
                                          uint32_t a0, uint32_t a1, uint32_t a2, uint32_t a3,
                                          uint32_t b0, uint32_t b1) {
    asm volatile(
        "mma.sync.aligned.m16n8k16.row.col.f32.f16.f16.f32 "
        "{%0,%1,%2,%3}, {%4,%5,%6,%7}, {%8,%9}, {%0,%1,%2,%3};"
        : "+f"(c[0]), "+f"(c[1]), "+f"(c[2]), "+f"(c[3])
        : "r"(a0), "r"(a1), "r"(a2), "r"(a3), "r"(b0), "r"(b1));
}

__device__ __forceinline__ uint32_t pkf16(float lo, float hi) {
    uint32_t r;
    asm("cvt.rn.f16x2.f32 %0, %1, %2;" : "=r"(r) : "f"(hi), "f"(lo));
    return r;
}

__device__ __forceinline__ float ex2(float x) {
    float r;
    asm("ex2.approx.f32 %0, %1;" : "=f"(r) : "f"(x));
    return r;
}

__device__ __forceinline__ uint32_t smem_u32(const void* p) {
    uint32_t a;
    asm("{ .reg .u64 t; cvta.to.shared.u64 t, %1; cvt.u32.u64 %0, t; }"
        : "=r"(a) : "l"(p));
    return a;
}

__device__ __forceinline__ void cp_async16(uint32_t dst, const void* src) {
    asm volatile("cp.async.cg.shared.global [%0], [%1], 16;"
                 :: "r"(dst), "l"(src) : "memory");
}

// ===========================================================================
// mma.sync split-bf16 GEMM:  C[M,N] = A[M,K] @ B[N,K]^T,  K = 1024
// batched via blockIdx.z with element strides sA/sB/sC.
// ===========================================================================
#define TCB_SMEM 65536

__global__ __launch_bounds__(256, 1)
void tc_gemm_kernel(const float* __restrict__ A, const float* __restrict__ B,
                    float* __restrict__ C, int ldc,
                    size_t sA, size_t sB, size_t sC)
{
    extern __shared__ char sm[];
    A += blockIdx.z * sA;
    B += blockIdx.z * sB;
    C += blockIdx.z * sC;
    const int tid  = threadIdx.x;
    const int lane = tid & 31;
    const int wid  = tid >> 5;
    const int wm   = (wid >> 2) * 64;
    const int wn   = (wid & 3) * 32;
    const int m0 = blockIdx.y * 128;
    const int n0 = blockIdx.x * 128;
    const int pl = lane ^ (lane >> 3);

    float acc[4][4][4];
#pragma unroll
    for (int i = 0; i < 4; i++)
#pragma unroll
        for (int j = 0; j < 4; j++)
#pragma unroll
            for (int q = 0; q < 4; q++) acc[i][j][q] = 0.f;

    float4 ra[4], rb[4];

#define LDG_CHUNK(k0)                                                          \
    {                                                                          \
        _Pragma("unroll")                                                      \
        for (int i = 0; i < 4; i++) {                                          \
            int idx = i * 256 + tid;                                           \
            int r = idx >> 3, c4 = (idx & 7) << 2;                             \
            ra[i] = *reinterpret_cast<const float4*>(                          \
                &A[(size_t)(m0 + r) * 1024 + (k0) + c4]);                      \
            rb[i] = *reinterpret_cast<const float4*>(                          \
                &B[(size_t)(n0 + r) * 1024 + (k0) + c4]);                      \
        }                                                                      \
    }

#define STS_CHUNK(bufp)                                                        \
    {                                                                          \
        char* _buf = (bufp);                                                   \
        _Pragma("unroll")                                                      \
        for (int i = 0; i < 4; i++) {                                          \
            int idx = i * 256 + tid;                                           \
            int r = idx >> 3, c4 = (idx & 7) << 2;                             \
            int kb = c4 >> 4, kk = c4 & 15;                                    \
            int rr = r & 15, mb = r >> 4;                                      \
            int s  = ((rr & 7) << 2) + ((kk & 7) >> 1);                        \
            int ps  = s ^ (s >> 3);                                            \
            int ps1 = (s + 1) ^ ((s + 1) >> 3);                                \
            int rg = (kk >> 3) + ((rr >> 3) << 1);                             \
            uint4 sp = split4(ra[i]);                                          \
            char* ab = _buf + (((mb << 1) + kb) << 9) + (rg << 2);             \
            *(uint32_t*)(ab + ps  * 16)        = sp.x;                         \
            *(uint32_t*)(ab + ps1 * 16)        = sp.y;                         \
            *(uint32_t*)(ab + 8192 + ps  * 16) = sp.z;                         \
            *(uint32_t*)(ab + 8192 + ps1 * 16) = sp.w;                         \
            int nn = r & 7, nb = r >> 3;                                       \
            int sb  = (nn << 2) + ((kk & 7) >> 1);                             \
            int psb  = sb ^ (sb >> 3);                                         \
            int psb1 = (sb + 1) ^ ((sb + 1) >> 3);                             \
            int rgb = kk >> 3;                                                 \
            uint4 sq = split4(rb[i]);                                          \
            char* bb = _buf + 16384 + (((nb << 1) + kb) << 9) + (rgb << 2);    \
            *(uint32_t*)(bb + psb  * 16)     = sq.x;                           \
            *(uint32_t*)(bb + psb1 * 16)     = sq.y;                           \
            *(uint32_t*)(bb + psb  * 16 + 8) = sq.z;                           \
            *(uint32_t*)(bb + psb1 * 16 + 8) = sq.w;                           \
        }                                                                      \
    }

#define COMPUTE_CHUNK(bufp)                                                    \
    {                                                                          \
        const char* _buf = (bufp);                                             \
        _Pragma("unroll")                                                      \
        for (int kb = 0; kb < 2; kb++) {                                       \
            uint4 ah[4], al[4], bq[4];                                         \
            _Pragma("unroll")                                                  \
            for (int am = 0; am < 4; am++) {                                   \
                const char* p = _buf + (((((wm >> 4) + am) << 1) + kb) << 9)   \
                                + pl * 16;                                     \
                ah[am] = *(const uint4*)p;                                     \
                al[am] = *(const uint4*)(p + 8192);                            \
            }                                                                  \
            _Pragma("unroll")                                                  \
            for (int bn = 0; bn < 4; bn++) {                                   \
                const char* p = _buf + 16384                                   \
                                + (((((wn >> 3) + bn) << 1) + kb) << 9)        \
                                + pl * 16;                                     \
                bq[bn] = *(const uint4*)p;                                     \
            }                                                                  \
            _Pragma("unroll")                                                  \
            for (int am = 0; am < 4; am++)                                     \
                _Pragma("unroll")                                              \
                for (int bn = 0; bn < 4; bn++) {                               \
                    float* c = acc[am][bn];                                    \
                    mma16816(c, ah[am].x, ah[am].z, ah[am].y, ah[am].w,        \
                             bq[bn].x, bq[bn].y);                              \
                    mma16816(c, ah[am].x, ah[am].z, ah[am].y, ah[am].w,        \
                             bq[bn].z, bq[bn].w);                              \
                    mma16816(c, al[am].x, al[am].z, al[am].y, al[am].w,        \
                             bq[bn].x, bq[bn].y);                              \
                }                                                              \
        }                                                                      \
    }

    LDG_CHUNK(0);
    STS_CHUNK(sm);
    __syncthreads();

    for (int ch = 0; ch < 32; ch++) {
        if (ch < 31) LDG_CHUNK((ch + 1) * 32);
        COMPUTE_CHUNK(sm + (ch & 1) * 32768);
        if (ch < 31) {
            STS_CHUNK(sm + ((ch + 1) & 1) * 32768);
            __syncthreads();
        }
    }

#pragma unroll
    for (int am = 0; am < 4; am++)
#pragma unroll
        for (int bn = 0; bn < 4; bn++) {
            const float* c = acc[am][bn];
            int row = m0 + wm + am * 16 + (lane >> 2);
            int col = n0 + wn + bn * 8 + ((lane & 3) << 1);
            *reinterpret_cast<float2*>(&C[(size_t)row * ldc + col]) =
                make_float2(c[0], c[1]);
            *reinterpret_cast<float2*>(&C[(size_t)(row + 8) * ldc + col]) =
                make_float2(c[2], c[3]);
        }
#undef LDG_CHUNK
#undef STS_CHUNK
#undef COMPUTE_CHUNK
}

// ---------------------------------------------------------------------------
// Batched 1024x1024 transpose: z=0 -> RT = R^T; z=1..3 -> WT_i = W_i^T
// ---------------------------------------------------------------------------
__global__ __launch_bounds__(256)
void transpose_kernel(const float* __restrict__ R,
                      const float* __restrict__ Wq,
                      const float* __restrict__ Wk,
                      const float* __restrict__ Wv,
                      float* __restrict__ RT, float* __restrict__ WT)
{
    __shared__ float t[32][33];
    const int z = blockIdx.z;
    const float* src = (z == 0) ? R : (z == 1) ? Wq : (z == 2) ? Wk : Wv;
    float* dst = (z == 0) ? RT : (WT + (size_t)(z - 1) * DD * DD);

    const int x0 = blockIdx.x * 32;
    const int y0 = blockIdx.y * 32;
    const int tx = threadIdx.x & 31;
    const int ty = threadIdx.x >> 5;   // 0..7

#pragma unroll
    for (int i = 0; i < 4; i++)
        t[ty + i * 8][tx] = src[(size_t)(y0 + ty + i * 8) * DD + x0 + tx];
    __syncthreads();
#pragma unroll
    for (int i = 0; i < 4; i++)
        dst[(size_t)(x0 + ty + i * 8) * DD + y0 + tx] = t[tx][ty + i * 8];
}

// ---------------------------------------------------------------------------
// Pack K,V (fp32 in g_QKV) into fp16 fragment-layout global blocks.
// Grid (32 ch, 16 h, 2 b), 256 threads. Per (b,h,ch): 64 keys x 64 dims.
// K block (nb=key>>3, kb=d>>4): word at L*2+w, L=((key&7)<<2)|((d>>1)&3),
//   w=(d>>3)&1, value = f16x2(K[key][d_even], K[key][d_even+1])
// V block (nb=dim>>3, kt=key>>4): L=((dim&7)<<2)|(kp&3), w=(kp>>2)&1,
//   value = f16x2(V[2kp][dim], V[2kp+1][dim])
// ---------------------------------------------------------------------------
__global__ __launch_bounds__(256)
void pack_kv_kernel(const float* __restrict__ QKV,
                    uint32_t* __restrict__ Kh, uint32_t* __restrict__ Vh)
{
    __shared__ float st[64 * 72];
    const int ch = blockIdx.x, h = blockIdx.y, b = blockIdx.z;
    const int tid = threadIdx.x;
    const size_t rowbase = (size_t)(b * LL + ch * 64) * QKV_LD;
    const int grp = ((b * HH + h) * 32 + ch) * 32;   // block index base

    // ---- K ----
#pragma unroll
    for (int i = 0; i < 4; i++) {
        int idx = i * 256 + tid;
        int key = idx >> 4, c4 = (idx & 15) << 2;
        *reinterpret_cast<float4*>(&st[key * 72 + c4]) =
            *reinterpret_cast<const float4*>(
                &QKV[rowbase + (size_t)key * QKV_LD + DD + h * HD + c4]);
    }
    __syncthreads();
#pragma unroll
    for (int i = 0; i < 8; i++) {
        int wi = i * 256 + tid;
        int key = wi >> 5, d2 = wi & 31, d = d2 * 2;
        uint32_t word = pkf16(st[key * 72 + d], st[key * 72 + d + 1]);
        int nb = key >> 3, kb = d >> 4;
        int L = ((key & 7) << 2) | (d2 & 3);
        int w = (d2 >> 2) & 1;
        Kh[(size_t)(grp + nb * 4 + kb) * 64 + L * 2 + w] = word;
    }
    __syncthreads();

    // ---- V ----
#pragma unroll
    for (int i = 0; i < 4; i++) {
        int idx = i * 256 + tid;
        int key = idx >> 4, c4 = (idx & 15) << 2;
        *reinterpret_cast<float4*>(&st[key * 72 + c4]) =
            *reinterpret_cast<const float4*>(
                &QKV[rowbase + (size_t)key * QKV_LD + 2 * DD + h * HD + c4]);
    }
    __syncthreads();
#pragma unroll
    for (int i = 0; i < 8; i++) {
        int wi = i * 256 + tid;
        int dim = wi >> 5, kp = wi & 31, key = kp * 2;
        uint32_t word = pkf16(st[key * 72 + dim], st[(key + 1) * 72 + dim]);
        int nb = dim >> 3, kt = kp >> 3;
        int p = kp & 7;
        int L = ((dim & 7) << 2) | (p & 3);
        int w = p >> 2;
        Vh[(size_t)(grp + nb * 4 + kt) * 64 + L * 2 + w] = word;
    }
}

// ===========================================================================
// Tensor-core flash attention v2: packed fp16 K/V streamed via cp.async.
// Grid (16 qtiles, 16 h, 2 b), 256 threads = 8 warps x 16 rows.
// SMEM: 2 x (8KB K + 8KB V). Conflict-free LDS.64 fragment reads.
// ===========================================================================
__global__ __launch_bounds__(256, 2)
void flash_attn_tc2(const float* __restrict__ QKV,
                    const uint32_t* __restrict__ Kh,
                    const uint32_t* __restrict__ Vh,
                    const float* __restrict__ entangle,
                    float* __restrict__ O)
{
    __shared__ char sbuf[2 * 16384];
    const uint32_t sb0 = smem_u32(sbuf);

    const int b  = blockIdx.z;
    const int h  = blockIdx.y;
    const int qt = blockIdx.x;
    const int tid  = threadIdx.x;
    const int lane = tid & 31;
    const int wid  = tid >> 5;
    const int t = lane & 3;
    const int r = lane >> 2;

    const float scale = entangle[h] * 0.125f * 1.44269504f;

    // ---- Q fragments ----
    const int mrow = b * LL + qt * 128 + wid * 16 + r;
    const float* q0p = QKV + (size_t)mrow * QKV_LD + h * HD;
    const float* q8p = q0p + (size_t)8 * QKV_LD;
    uint32_t qa[4][4];
#pragma unroll
    for (int kb = 0; kb < 4; kb++) {
        const int c = kb * 16 + 2 * t;
        float2 v0a = *reinterpret_cast<const float2*>(q0p + c);
        float2 v8a = *reinterpret_cast<const float2*>(q8p + c);
        float2 v0b = *reinterpret_cast<const float2*>(q0p + c + 8);
        float2 v8b = *reinterpret_cast<const float2*>(q8p + c + 8);
        qa[kb][0] = pkf16(v0a.x * scale, v0a.y * scale);
        qa[kb][1] = pkf16(v8a.x * scale, v8a.y * scale);
        qa[kb][2] = pkf16(v0b.x * scale, v0b.y * scale);
        qa[kb][3] = pkf16(v8b.x * scale, v8b.y * scale);
    }

    float oc[8][4];
#pragma unroll
    for (int i = 0; i < 8; i++)
#pragma unroll
        for (int j = 0; j < 4; j++) oc[i][j] = 0.f;
    float l0 = 0.f, l1 = 0.f;
    float mx0 = -1e30f, mx1 = -1e30f;

    const char* Kg = reinterpret_cast<const char*>(Kh)
                     + (size_t)((b * HH + h) * 32) * 8192;
    const char* Vg = reinterpret_cast<const char*>(Vh)
                     + (size_t)((b * HH + h) * 32) * 8192;

#define FA_PREFETCH(ch)                                                        \
    {                                                                          \
        uint32_t d = sb0 + ((ch) & 1) * 16384 + tid * 16;                      \
        const char* ks = Kg + (size_t)(ch) * 8192 + tid * 16;                  \
        const char* vs = Vg + (size_t)(ch) * 8192 + tid * 16;                  \
        cp_async16(d,           ks);                                           \
        cp_async16(d + 4096,    ks + 4096);                                    \
        cp_async16(d + 8192,    vs);                                           \
        cp_async16(d + 12288,   vs + 4096);                                    \
        asm volatile("cp.async.commit_group;" ::: "memory");                   \
    }

    FA_PREFETCH(0);

    for (int ch = 0; ch < 32; ch++) {
        if (ch < 31) {
            FA_PREFETCH(ch + 1);
            asm volatile("cp.async.wait_group 1;" ::: "memory");
        } else {
            asm volatile("cp.async.wait_group 0;" ::: "memory");
        }
        __syncthreads();

        const char* kb_ = sbuf + (ch & 1) * 16384;
        const char* vb_ = kb_ + 8192;

        // ---- QK ----
        float sc[8][4];
#pragma unroll
        for (int nb = 0; nb < 8; nb++) {
            sc[nb][0] = sc[nb][1] = sc[nb][2] = sc[nb][3] = 0.f;
#pragma unroll
            for (int kb = 0; kb < 4; kb++) {
                uint2 bb = *(const uint2*)(kb_ + ((nb << 2) | kb) * 256 + lane * 8);
                mma16816h(sc[nb], qa[kb][0], qa[kb][1], qa[kb][2], qa[kb][3],
                          bb.x, bb.y);
            }
        }

        // ---- online softmax (log2 domain) ----
        float cm0 = mx0, cm1 = mx1;
#pragma unroll
        for (int nb = 0; nb < 8; nb++) {
            cm0 = fmaxf(cm0, fmaxf(sc[nb][0], sc[nb][1]));
            cm1 = fmaxf(cm1, fmaxf(sc[nb][2], sc[nb][3]));
        }
        cm0 = fmaxf(cm0, __shfl_xor_sync(0xffffffffu, cm0, 1));
        cm0 = fmaxf(cm0, __shfl_xor_sync(0xffffffffu, cm0, 2));
        cm1 = fmaxf(cm1, __shfl_xor_sync(0xffffffffu, cm1, 1));
        cm1 = fmaxf(cm1, __shfl_xor_sync(0xffffffffu, cm1, 2));
        float corr0 = ex2(mx0 - cm0), corr1 = ex2(mx1 - cm1);
        mx0 = cm0; mx1 = cm1;
        float sum0 = 0.f, sum1 = 0.f;
#pragma unroll
        for (int nb = 0; nb < 8; nb++) {
            sc[nb][0] = ex2(sc[nb][0] - mx0); sum0 += sc[nb][0];
            sc[nb][1] = ex2(sc[nb][1] - mx0); sum0 += sc[nb][1];
            sc[nb][2] = ex2(sc[nb][2] - mx1); sum1 += sc[nb][2];
            sc[nb][3] = ex2(sc[nb][3] - mx1); sum1 += sc[nb][3];
        }
        sum0 += __shfl_xor_sync(0xffffffffu, sum0, 1);
        sum0 += __shfl_xor_sync(0xffffffffu, sum0, 2);
        sum1 += __shfl_xor_sync(0xffffffffu, sum1, 1);
        sum1 += __shfl_xor_sync(0xffffffffu, sum1, 2);
        l0 = l0 * corr0 + sum0;
        l1 = l1 * corr1 + sum1;
#pragma unroll
        for (int nb = 0; nb < 8; nb++) {
            oc[nb][0] *= corr0; oc[nb][1] *= corr0;
            oc[nb][2] *= corr1; oc[nb][3] *= corr1;
        }

        // ---- PV ----
#pragma unroll
        for (int kt = 0; kt < 4; kt++) {
            uint32_t pa0 = pkf16(sc[2 * kt][0],     sc[2 * kt][1]);
            uint32_t pa1 = pkf16(sc[2 * kt][2],     sc[2 * kt][3]);
            uint32_t pa2 = pkf16(sc[2 * kt + 1][0], sc[2 * kt + 1][1]);
            uint32_t pa3 = pkf16(sc[2 * kt + 1][2], sc[2 * kt + 1][3]);
#pragma unroll
            for (int nb = 0; nb < 8; nb++) {
                uint2 vv = *(const uint2*)(vb_ + ((nb << 2) | kt) * 256 + lane * 8);
                mma16816h(oc[nb], pa0, pa1, pa2, pa3, vv.x, vv.y);
            }
        }

        if (ch < 31) __syncthreads();
    }

    // ---- epilogue ----
    const float inv0 = 1.f / l0;
    const float inv1 = 1.f / l1;
    float* o0 = O + (size_t)mrow * DD + h * HD;
    float* o8 = o0 + (size_t)8 * DD;
#pragma unroll
    for (int nb = 0; nb < 8; nb++) {
        *reinterpret_cast<float2*>(o0 + nb * 8 + 2 * t) =
            make_float2(oc[nb][0] * inv0, oc[nb][1] * inv0);
        *reinterpret_cast<float2*>(o8 + nb * 8 + 2 * t) =
            make_float2(oc[nb][2] * inv1, oc[nb][3] * inv1);
    }
#undef FA_PREFETCH
}

// ---------------------------------------------------------------------------
// Launch
// ---------------------------------------------------------------------------
extern "C" void kernel_launch(void* const* d_in, const int* in_sizes, int n_in,
                              void* d_out, int out_size)
{
    const float* X   = (const float*)d_in[0];
    const float* R   = (const float*)d_in[1];
    const float* ent = (const float*)d_in[2];
    const float* Wq  = (const float*)d_in[3];
    const float* Wk  = (const float*)d_in[4];
    const float* Wv  = (const float*)d_in[5];
    const float* Wo  = (const float*)d_in[6];
    float* out = (float*)d_out;

    float *wfoldT, *qkv, *ao, *rt, *wt;
    uint32_t *kh, *vh;
    cudaGetSymbolAddress((void**)&wfoldT, g_WfoldT);
    cudaGetSymbolAddress((void**)&qkv,    g_QKV);
    cudaGetSymbolAddress((void**)&ao,     g_AO);
    cudaGetSymbolAddress((void**)&rt,     g_RT);
    cudaGetSymbolAddress((void**)&wt,     g_WT);
    cudaGetSymbolAddress((void**)&kh,     g_Kh);
    cudaGetSymbolAddress((void**)&vh,     g_Vh);

    static int smem_set = 0;
    if (!smem_set) {
        cudaFuncSetAttribute(tc_gemm_kernel,
                             cudaFuncAttributeMaxDynamicSharedMemorySize, TCB_SMEM);
        smem_set = 1;
    }

    // 1) Transposes: RT = R^T, WT_i = W_i^T
    {
        dim3 g(32, 32, 4);
        transpose_kernel<<<g, 256>>>(R, Wq, Wk, Wv, rt, wt);
    }

    // 2) Folds on tensor cores (batched): WfoldT_i = RT @ WT_i^T = R^T W_i
    {
        dim3 g(8, 8, 3);
        tc_gemm_kernel<<<g, 256, TCB_SMEM>>>(rt, wt, wfoldT, DD,
                                             0, (size_t)DD * DD, (size_t)DD * DD);
    }

    // 3) Fused QKV projection: QKV = X @ WfoldT^T
    {
        dim3 g(24, 32, 1);
        tc_gemm_kernel<<<g, 256, TCB_SMEM>>>(X, wfoldT, qkv, QKV_LD, 0, 0, 0);
    }

    // 4) Pack K/V to fp16 fragment layout
    {
        dim3 g(32, HH, BB);
        pack_kv_kernel<<<g, 256>>>(qkv, kh, vh);
    }

    // 5) Flash attention v2
    {
        dim3 g(LL / 128, HH, BB);
        flash_attn_tc2<<<g, 256>>>(qkv, kh, vh, ent, ao);
    }

    // 6) Output projection: out = AO @ Wo^T
    {
        dim3 g(8, 32, 1);
        tc_gemm_kernel<<<g, 256, TCB_SMEM>>>(ao, Wo, out, DD, 0, 0, 0);
    }
}

// round 7
// speedup vs baseline: 5.5918x; 1.2013x over previous
#include <cuda_runtime.h>
#include <cuda_bf16.h>
#include <math.h>
#include <stdint.h>

// Problem constants
#define BB   2
#define LL   2048
#define DD   1024
#define HH   16
#define HD   64
#define MM   (BB*LL)          // 4096
#define QKV_LD (3*DD)         // fused QKV row stride

// Scratch (static device memory -- no allocations allowed)
__device__ float g_WfoldT[3 * DD * DD];   // R^T @ W_i  fp32 ([n][k])
__device__ float g_QKV[MM * 3 * DD];      // fused [M][3072]: Q | K | V
__device__ float g_RT[DD * DD];           // R^T
__device__ float g_WT[3 * DD * DD];       // W_i^T
// fp16 fragment-layout K/V for attention: per (b,h,chunk64) 32 blocks of 256B
__device__ uint32_t g_Kh[BB * HH * 32 * 32 * 64];   // 8MB
__device__ uint32_t g_Vh[BB * HH * 32 * 32 * 64];   // 8MB
// packed bf16 hi/lo fragment-layout GEMM operands
// A-pack: region per (mtile,kpair) = 16KB = 8 mb x 2 kb x [hi512|lo512]
// B-pack: region per (ntile,kpair) = 16KB = 16 nb x 2 kb x [hi256|lo256]
__device__ uint32_t g_Xpk [32 * 32 * 4096];   // X packed  (16MB)
__device__ uint32_t g_AOpk[32 * 32 * 4096];   // attention out packed (16MB)
__device__ uint32_t g_Wfpk[24 * 32 * 4096];   // WfoldT packed (12MB)
__device__ uint32_t g_Wopk[ 8 * 32 * 4096];   // Wo packed (4MB)

// ===========================================================================
// helpers
// ===========================================================================
__device__ __forceinline__ uint4 split4(float4 v) {
    uint32_t h01, h23;
    asm("cvt.rn.bf16x2.f32 %0, %1, %2;" : "=r"(h01) : "f"(v.y), "f"(v.x));
    asm("cvt.rn.bf16x2.f32 %0, %1, %2;" : "=r"(h23) : "f"(v.w), "f"(v.z));
    float h0 = __uint_as_float(h01 << 16);
    float h1 = __uint_as_float(h01 & 0xFFFF0000u);
    float h2 = __uint_as_float(h23 << 16);
    float h3 = __uint_as_float(h23 & 0xFFFF0000u);
    uint32_t l01, l23;
    asm("cvt.rn.bf16x2.f32 %0, %1, %2;" : "=r"(l01) : "f"(v.y - h1), "f"(v.x - h0));
    asm("cvt.rn.bf16x2.f32 %0, %1, %2;" : "=r"(l23) : "f"(v.w - h3), "f"(v.z - h2));
    return make_uint4(h01, h23, l01, l23);
}

// split two fp32 into (hi bf16x2, lo bf16x2)
__device__ __forceinline__ uint2 split2(float a, float b) {
    uint32_t h;
    asm("cvt.rn.bf16x2.f32 %0, %1, %2;" : "=r"(h) : "f"(b), "f"(a));
    float ha = __uint_as_float(h << 16);
    float hb = __uint_as_float(h & 0xFFFF0000u);
    uint32_t l;
    asm("cvt.rn.bf16x2.f32 %0, %1, %2;" : "=r"(l) : "f"(b - hb), "f"(a - ha));
    return make_uint2(h, l);
}

__device__ __forceinline__ void mma16816(float* c,
                                         uint32_t a0, uint32_t a1, uint32_t a2, uint32_t a3,
                                         uint32_t b0, uint32_t b1) {
    asm volatile(
        "mma.sync.aligned.m16n8k16.row.col.f32.bf16.bf16.f32 "
        "{%0,%1,%2,%3}, {%4,%5,%6,%7}, {%8,%9}, {%0,%1,%2,%3};"
        : "+f"(c[0]), "+f"(c[1]), "+f"(c[2]), "+f"(c[3])
        : "r"(a0), "r"(a1), "r"(a2), "r"(a3), "r"(b0), "r"(b1));
}

__device__ __forceinline__ void mma16816h(float* c,
                                          uint32_t a0, uint32_t a1, uint32_t a2, uint32_t a3,
                                          uint32_t b0, uint32_t b1) {
    asm volatile(
        "mma.sync.aligned.m16n8k16.row.col.f32.f16.f16.f32 "
        "{%0,%1,%2,%3}, {%4,%5,%6,%7}, {%8,%9}, {%0,%1,%2,%3};"
        : "+f"(c[0]), "+f"(c[1]), "+f"(c[2]), "+f"(c[3])
        : "r"(a0), "r"(a1), "r"(a2), "r"(a3), "r"(b0), "r"(b1));
}

__device__ __forceinline__ uint32_t pkf16(float lo, float hi) {
    uint32_t r;
    asm("cvt.rn.f16x2.f32 %0, %1, %2;" : "=r"(r) : "f"(hi), "f"(lo));
    return r;
}

__device__ __forceinline__ float ex2(float x) {
    float r;
    asm("ex2.approx.f32 %0, %1;" : "=f"(r) : "f"(x));
    return r;
}

__device__ __forceinline__ uint32_t smem_u32(const void* p) {
    uint32_t a;
    asm("{ .reg .u64 t; cvta.to.shared.u64 t, %1; cvt.u32.u64 %0, t; }"
        : "=r"(a) : "l"(p));
    return a;
}

__device__ __forceinline__ void cp_async16(uint32_t dst, const void* src) {
    asm volatile("cp.async.cg.shared.global [%0], [%1], 16;"
                 :: "r"(dst), "l"(src) : "memory");
}

// ===========================================================================
// Operand pack kernels (fp32 row-major, ld=1024 -> packed fragment layout)
// ===========================================================================
__global__ __launch_bounds__(256)
void pack_a_kernel(const float* __restrict__ src, uint32_t* __restrict__ dst)
{
    const int kpair = blockIdx.x, mtile = blockIdx.y, tid = threadIdx.x;
    uint32_t* region = dst + ((size_t)mtile * 32 + kpair) * 4096;
#pragma unroll
    for (int i = 0; i < 4; i++) {
        int idx = i * 256 + tid;
        int row = idx >> 3, c4 = (idx & 7) << 2;
        float4 v = *reinterpret_cast<const float4*>(
            &src[(size_t)(mtile * 128 + row) * 1024 + kpair * 32 + c4]);
        uint4 sp = split4(v);
        int mb = row >> 4, r = row & 7;
        int islow = ((row & 15) < 8);
        int kb = c4 >> 4, kk = c4 & 15;
        int khigh = (kk >> 3) & 1, t = (kk & 7) >> 1;
        uint32_t* base = region + (mb * 2 + kb) * 256;
        int aidx = islow ? (khigh ? 2 : 0) : (khigh ? 3 : 1);
        base[(r * 4 + t)     * 4 + aidx]       = sp.x;
        base[(r * 4 + t + 1) * 4 + aidx]       = sp.y;
        base[128 + (r * 4 + t)     * 4 + aidx] = sp.z;
        base[128 + (r * 4 + t + 1) * 4 + aidx] = sp.w;
    }
}

__global__ __launch_bounds__(256)
void pack_b_kernel(const float* __restrict__ src, uint32_t* __restrict__ dst)
{
    const int kpair = blockIdx.x, ntile = blockIdx.y, tid = threadIdx.x;
    uint32_t* region = dst + ((size_t)ntile * 32 + kpair) * 4096;
#pragma unroll
    for (int i = 0; i < 4; i++) {
        int idx = i * 256 + tid;
        int row = idx >> 3, c4 = (idx & 7) << 2;
        float4 v = *reinterpret_cast<const float4*>(
            &src[(size_t)(ntile * 128 + row) * 1024 + kpair * 32 + c4]);
        uint4 sp = split4(v);
        int nb = row >> 3;
        int kb = c4 >> 4, kk = c4 & 15;
        int khigh = (kk >> 3) & 1, t = (kk & 7) >> 1;
        int L = ((row & 7) << 2) + t;
        uint32_t* base = region + (nb * 2 + kb) * 128;
        base[L * 2 + khigh]            = sp.x;
        base[(L + 1) * 2 + khigh]      = sp.y;
        base[64 + L * 2 + khigh]       = sp.z;
        base[64 + (L + 1) * 2 + khigh] = sp.w;
    }
}

// ===========================================================================
// Packed-operand split-bf16 GEMM: C[M,N] = A @ B^T, K=1024.
// Operands streamed by cp.async (identity copy, fragment layout).
// Grid (ntile, mtile), 256 thr = 8 warps (2x4) of 64x32 tiles, BK=32, 2 bufs.
// ===========================================================================
#define PKG_SMEM 65536

__global__ __launch_bounds__(256)
void pk_gemm(const uint32_t* __restrict__ A, const uint32_t* __restrict__ B,
             float* __restrict__ C, int ldc)
{
    extern __shared__ char sm[];
    const uint32_t sb = smem_u32(sm);
    const int tid  = threadIdx.x;
    const int lane = tid & 31;
    const int wid  = tid >> 5;
    const int wm   = (wid >> 2) * 64;
    const int wn   = (wid & 3) * 32;

    const char* Ag = reinterpret_cast<const char*>(A + (size_t)blockIdx.y * 32 * 4096);
    const char* Bg = reinterpret_cast<const char*>(B + (size_t)blockIdx.x * 32 * 4096);

    float acc[4][4][4];
#pragma unroll
    for (int i = 0; i < 4; i++)
#pragma unroll
        for (int j = 0; j < 4; j++)
#pragma unroll
            for (int q = 0; q < 4; q++) acc[i][j][q] = 0.f;

#define PKG_PF(ch)                                                             \
    {                                                                          \
        uint32_t d = sb + ((ch) & 1) * 32768 + tid * 16;                       \
        const char* a = Ag + (size_t)(ch) * 16384 + tid * 16;                  \
        const char* b = Bg + (size_t)(ch) * 16384 + tid * 16;                  \
        cp_async16(d,          a);                                             \
        cp_async16(d + 4096,   a + 4096);                                      \
        cp_async16(d + 8192,   a + 8192);                                      \
        cp_async16(d + 12288,  a + 12288);                                     \
        cp_async16(d + 16384,  b);                                             \
        cp_async16(d + 20480,  b + 4096);                                      \
        cp_async16(d + 24576,  b + 8192);                                      \
        cp_async16(d + 28672,  b + 12288);                                     \
        asm volatile("cp.async.commit_group;" ::: "memory");                   \
    }

    PKG_PF(0);

    for (int ch = 0; ch < 32; ch++) {
        if (ch < 31) {
            PKG_PF(ch + 1);
            asm volatile("cp.async.wait_group 1;" ::: "memory");
        } else {
            asm volatile("cp.async.wait_group 0;" ::: "memory");
        }
        __syncthreads();

        const char* bufA = sm + (ch & 1) * 32768;
        const char* bufB = bufA + 16384;
#pragma unroll
        for (int kb = 0; kb < 2; kb++) {
            uint4 ah[4], al[4];
            uint2 bh[4], bl[4];
#pragma unroll
            for (int am = 0; am < 4; am++) {
                const char* p = bufA + ((((wm >> 4) + am) * 2 + kb) << 10) + lane * 16;
                ah[am] = *(const uint4*)p;
                al[am] = *(const uint4*)(p + 512);
            }
#pragma unroll
            for (int bn = 0; bn < 4; bn++) {
                const char* q = bufB + ((((wn >> 3) + bn) * 2 + kb) << 9) + lane * 8;
                bh[bn] = *(const uint2*)q;
                bl[bn] = *(const uint2*)(q + 256);
            }
#pragma unroll
            for (int am = 0; am < 4; am++)
#pragma unroll
                for (int bn = 0; bn < 4; bn++) {
                    float* c = acc[am][bn];
                    mma16816(c, ah[am].x, ah[am].y, ah[am].z, ah[am].w,
                             bh[bn].x, bh[bn].y);
                    mma16816(c, ah[am].x, ah[am].y, ah[am].z, ah[am].w,
                             bl[bn].x, bl[bn].y);
                    mma16816(c, al[am].x, al[am].y, al[am].z, al[am].w,
                             bh[bn].x, bh[bn].y);
                }
        }
        if (ch < 31) __syncthreads();
    }

    const int m0 = blockIdx.y * 128;
    const int n0 = blockIdx.x * 128;
#pragma unroll
    for (int am = 0; am < 4; am++)
#pragma unroll
        for (int bn = 0; bn < 4; bn++) {
            const float* c = acc[am][bn];
            int row = m0 + wm + am * 16 + (lane >> 2);
            int col = n0 + wn + bn * 8 + ((lane & 3) << 1);
            *reinterpret_cast<float2*>(&C[(size_t)row * ldc + col]) =
                make_float2(c[0], c[1]);
            *reinterpret_cast<float2*>(&C[(size_t)(row + 8) * ldc + col]) =
                make_float2(c[2], c[3]);
        }
#undef PKG_PF
}

// ===========================================================================
// Old convert-in-kernel split-bf16 GEMM — kept only for the 3 weight folds.
// ===========================================================================
#define TCB_SMEM 65536

__global__ __launch_bounds__(256, 1)
void tc_gemm_kernel(const float* __restrict__ A, const float* __restrict__ B,
                    float* __restrict__ C, int ldc,
                    size_t sA, size_t sB, size_t sC)
{
    extern __shared__ char sm[];
    A += blockIdx.z * sA;
    B += blockIdx.z * sB;
    C += blockIdx.z * sC;
    const int tid  = threadIdx.x;
    const int lane = tid & 31;
    const int wid  = tid >> 5;
    const int wm   = (wid >> 2) * 64;
    const int wn   = (wid & 3) * 32;
    const int m0 = blockIdx.y * 128;
    const int n0 = blockIdx.x * 128;
    const int pl = lane ^ (lane >> 3);

    float acc[4][4][4];
#pragma unroll
    for (int i = 0; i < 4; i++)
#pragma unroll
        for (int j = 0; j < 4; j++)
#pragma unroll
            for (int q = 0; q < 4; q++) acc[i][j][q] = 0.f;

    float4 ra[4], rb[4];

#define LDG_CHUNK(k0)                                                          \
    {                                                                          \
        _Pragma("unroll")                                                      \
        for (int i = 0; i < 4; i++) {                                          \
            int idx = i * 256 + tid;                                           \
            int r = idx >> 3, c4 = (idx & 7) << 2;                             \
            ra[i] = *reinterpret_cast<const float4*>(                          \
                &A[(size_t)(m0 + r) * 1024 + (k0) + c4]);                      \
            rb[i] = *reinterpret_cast<const float4*>(                          \
                &B[(size_t)(n0 + r) * 1024 + (k0) + c4]);                      \
        }                                                                      \
    }

#define STS_CHUNK(bufp)                                                        \
    {                                                                          \
        char* _buf = (bufp);                                                   \
        _Pragma("unroll")                                                      \
        for (int i = 0; i < 4; i++) {                                          \
            int idx = i * 256 + tid;                                           \
            int r = idx >> 3, c4 = (idx & 7) << 2;                             \
            int kb = c4 >> 4, kk = c4 & 15;                                    \
            int rr = r & 15, mb = r >> 4;                                      \
            int s  = ((rr & 7) << 2) + ((kk & 7) >> 1);                        \
            int ps  = s ^ (s >> 3);                                            \
            int ps1 = (s + 1) ^ ((s + 1) >> 3);                                \
            int rg = (kk >> 3) + ((rr >> 3) << 1);                             \
            uint4 sp = split4(ra[i]);                                          \
            char* ab = _buf + (((mb << 1) + kb) << 9) + (rg << 2);             \
            *(uint32_t*)(ab + ps  * 16)        = sp.x;                         \
            *(uint32_t*)(ab + ps1 * 16)        = sp.y;                         \
            *(uint32_t*)(ab + 8192 + ps  * 16) = sp.z;                         \
            *(uint32_t*)(ab + 8192 + ps1 * 16) = sp.w;                         \
            int nn = r & 7, nb = r >> 3;                                       \
            int sb2 = (nn << 2) + ((kk & 7) >> 1);                             \
            int psb  = sb2 ^ (sb2 >> 3);                                       \
            int psb1 = (sb2 + 1) ^ ((sb2 + 1) >> 3);                           \
            int rgb = kk >> 3;                                                 \
            uint4 sq = split4(rb[i]);                                          \
            char* bb = _buf + 16384 + (((nb << 1) + kb) << 9) + (rgb << 2);    \
            *(uint32_t*)(bb + psb  * 16)     = sq.x;                           \
            *(uint32_t*)(bb + psb1 * 16)     = sq.y;                           \
            *(uint32_t*)(bb + psb  * 16 + 8) = sq.z;                           \
            *(uint32_t*)(bb + psb1 * 16 + 8) = sq.w;                           \
        }                                                                      \
    }

#define COMPUTE_CHUNK(bufp)                                                    \
    {                                                                          \
        const char* _buf = (bufp);                                             \
        _Pragma("unroll")                                                      \
        for (int kb = 0; kb < 2; kb++) {                                       \
            uint4 ah[4], al[4], bq[4];                                         \
            _Pragma("unroll")                                                  \
            for (int am = 0; am < 4; am++) {                                   \
                const char* p = _buf + (((((wm >> 4) + am) << 1) + kb) << 9)   \
                                + pl * 16;                                     \
                ah[am] = *(const uint4*)p;                                     \
                al[am] = *(const uint4*)(p + 8192);                            \
            }                                                                  \
            _Pragma("unroll")                                                  \
            for (int bn = 0; bn < 4; bn++) {                                   \
                const char* p = _buf + 16384                                   \
                                + (((((wn >> 3) + bn) << 1) + kb) << 9)        \
                                + pl * 16;                                     \
                bq[bn] = *(const uint4*)p;                                     \
            }                                                                  \
            _Pragma("unroll")                                                  \
            for (int am = 0; am < 4; am++)                                     \
                _Pragma("unroll")                                              \
                for (int bn = 0; bn < 4; bn++) {                               \
                    float* c = acc[am][bn];                                    \
                    mma16816(c, ah[am].x, ah[am].z, ah[am].y, ah[am].w,        \
                             bq[bn].x, bq[bn].y);                              \
                    mma16816(c, ah[am].x, ah[am].z, ah[am].y, ah[am].w,        \
                             bq[bn].z, bq[bn].w);                              \
                    mma16816(c, al[am].x, al[am].z, al[am].y, al[am].w,        \
                             bq[bn].x, bq[bn].y);                              \
                }                                                              \
        }                                                                      \
    }

    LDG_CHUNK(0);
    STS_CHUNK(sm);
    __syncthreads();

    for (int ch = 0; ch < 32; ch++) {
        if (ch < 31) LDG_CHUNK((ch + 1) * 32);
        COMPUTE_CHUNK(sm + (ch & 1) * 32768);
        if (ch < 31) {
            STS_CHUNK(sm + ((ch + 1) & 1) * 32768);
            __syncthreads();
        }
    }

#pragma unroll
    for (int am = 0; am < 4; am++)
#pragma unroll
        for (int bn = 0; bn < 4; bn++) {
            const float* c = acc[am][bn];
            int row = m0 + wm + am * 16 + (lane >> 2);
            int col = n0 + wn + bn * 8 + ((lane & 3) << 1);
            *reinterpret_cast<float2*>(&C[(size_t)row * ldc + col]) =
                make_float2(c[0], c[1]);
            *reinterpret_cast<float2*>(&C[(size_t)(row + 8) * ldc + col]) =
                make_float2(c[2], c[3]);
        }
#undef LDG_CHUNK
#undef STS_CHUNK
#undef COMPUTE_CHUNK
}

// ---------------------------------------------------------------------------
// Batched 1024x1024 transpose: z=0 -> RT = R^T; z=1..3 -> WT_i = W_i^T
// ---------------------------------------------------------------------------
__global__ __launch_bounds__(256)
void transpose_kernel(const float* __restrict__ R,
                      const float* __restrict__ Wq,
                      const float* __restrict__ Wk,
                      const float* __restrict__ Wv,
                      float* __restrict__ RT, float* __restrict__ WT)
{
    __shared__ float t[32][33];
    const int z = blockIdx.z;
    const float* src = (z == 0) ? R : (z == 1) ? Wq : (z == 2) ? Wk : Wv;
    float* dst = (z == 0) ? RT : (WT + (size_t)(z - 1) * DD * DD);

    const int x0 = blockIdx.x * 32;
    const int y0 = blockIdx.y * 32;
    const int tx = threadIdx.x & 31;
    const int ty = threadIdx.x >> 5;

#pragma unroll
    for (int i = 0; i < 4; i++)
        t[ty + i * 8][tx] = src[(size_t)(y0 + ty + i * 8) * DD + x0 + tx];
    __syncthreads();
#pragma unroll
    for (int i = 0; i < 4; i++)
        dst[(size_t)(x0 + ty + i * 8) * DD + y0 + tx] = t[tx][ty + i * 8];
}

// ---------------------------------------------------------------------------
// Pack K,V (fp32 in g_QKV) into fp16 fragment-layout global blocks.
// ---------------------------------------------------------------------------
__global__ __launch_bounds__(256)
void pack_kv_kernel(const float* __restrict__ QKV,
                    uint32_t* __restrict__ Kh, uint32_t* __restrict__ Vh)
{
    __shared__ float st[64 * 72];
    const int ch = blockIdx.x, h = blockIdx.y, b = blockIdx.z;
    const int tid = threadIdx.x;
    const size_t rowbase = (size_t)(b * LL + ch * 64) * QKV_LD;
    const int grp = ((b * HH + h) * 32 + ch) * 32;

    // ---- K ----
#pragma unroll
    for (int i = 0; i < 4; i++) {
        int idx = i * 256 + tid;
        int key = idx >> 4, c4 = (idx & 15) << 2;
        *reinterpret_cast<float4*>(&st[key * 72 + c4]) =
            *reinterpret_cast<const float4*>(
                &QKV[rowbase + (size_t)key * QKV_LD + DD + h * HD + c4]);
    }
    __syncthreads();
#pragma unroll
    for (int i = 0; i < 8; i++) {
        int wi = i * 256 + tid;
        int key = wi >> 5, d2 = wi & 31, d = d2 * 2;
        uint32_t word = pkf16(st[key * 72 + d], st[key * 72 + d + 1]);
        int nb = key >> 3, kb = d >> 4;
        int L = ((key & 7) << 2) | (d2 & 3);
        int w = (d2 >> 2) & 1;
        Kh[(size_t)(grp + nb * 4 + kb) * 64 + L * 2 + w] = word;
    }
    __syncthreads();

    // ---- V ----
#pragma unroll
    for (int i = 0; i < 4; i++) {
        int idx = i * 256 + tid;
        int key = idx >> 4, c4 = (idx & 15) << 2;
        *reinterpret_cast<float4*>(&st[key * 72 + c4]) =
            *reinterpret_cast<const float4*>(
                &QKV[rowbase + (size_t)key * QKV_LD + 2 * DD + h * HD + c4]);
    }
    __syncthreads();
#pragma unroll
    for (int i = 0; i < 8; i++) {
        int wi = i * 256 + tid;
        int dim = wi >> 5, kp = wi & 31, key = kp * 2;
        uint32_t word = pkf16(st[key * 72 + dim], st[(key + 1) * 72 + dim]);
        int nb = dim >> 3, kt = kp >> 3;
        int p = kp & 7;
        int L = ((dim & 7) << 2) | (p & 3);
        int w = p >> 2;
        Vh[(size_t)(grp + nb * 4 + kt) * 64 + L * 2 + w] = word;
    }
}

// ===========================================================================
// Tensor-core flash attention: packed fp16 K/V via cp.async.
// Epilogue writes AO directly as packed-A hi/lo bf16 fragments for pk_gemm.
// ===========================================================================
__global__ __launch_bounds__(256, 2)
void flash_attn_tc2(const float* __restrict__ QKV,
                    const uint32_t* __restrict__ Kh,
                    const uint32_t* __restrict__ Vh,
                    const float* __restrict__ entangle,
                    uint32_t* __restrict__ AOpk)
{
    __shared__ char sbuf[2 * 16384];
    const uint32_t sb0 = smem_u32(sbuf);

    const int b  = blockIdx.z;
    const int h  = blockIdx.y;
    const int qt = blockIdx.x;
    const int tid  = threadIdx.x;
    const int lane = tid & 31;
    const int wid  = tid >> 5;
    const int t = lane & 3;
    const int r = lane >> 2;

    const float scale = entangle[h] * 0.125f * 1.44269504f;

    // ---- Q fragments ----
    const int mrow = b * LL + qt * 128 + wid * 16 + r;
    const float* q0p = QKV + (size_t)mrow * QKV_LD + h * HD;
    const float* q8p = q0p + (size_t)8 * QKV_LD;
    uint32_t qa[4][4];
#pragma unroll
    for (int kb = 0; kb < 4; kb++) {
        const int c = kb * 16 + 2 * t;
        float2 v0a = *reinterpret_cast<const float2*>(q0p + c);
        float2 v8a = *reinterpret_cast<const float2*>(q8p + c);
        float2 v0b = *reinterpret_cast<const float2*>(q0p + c + 8);
        float2 v8b = *reinterpret_cast<const float2*>(q8p + c + 8);
        qa[kb][0] = pkf16(v0a.x * scale, v0a.y * scale);
        qa[kb][1] = pkf16(v8a.x * scale, v8a.y * scale);
        qa[kb][2] = pkf16(v0b.x * scale, v0b.y * scale);
        qa[kb][3] = pkf16(v8b.x * scale, v8b.y * scale);
    }

    float oc[8][4];
#pragma unroll
    for (int i = 0; i < 8; i++)
#pragma unroll
        for (int j = 0; j < 4; j++) oc[i][j] = 0.f;
    float l0 = 0.f, l1 = 0.f;
    float mx0 = -1e30f, mx1 = -1e30f;

    const char* Kg = reinterpret_cast<const char*>(Kh)
                     + (size_t)((b * HH + h) * 32) * 8192;
    const char* Vg = reinterpret_cast<const char*>(Vh)
                     + (size_t)((b * HH + h) * 32) * 8192;

#define FA_PREFETCH(ch)                                                        \
    {                                                                          \
        uint32_t d = sb0 + ((ch) & 1) * 16384 + tid * 16;                      \
        const char* ks = Kg + (size_t)(ch) * 8192 + tid * 16;                  \
        const char* vs = Vg + (size_t)(ch) * 8192 + tid * 16;                  \
        cp_async16(d,           ks);                                           \
        cp_async16(d + 4096,    ks + 4096);                                    \
        cp_async16(d + 8192,    vs);                                           \
        cp_async16(d + 12288,   vs + 4096);                                    \
        asm volatile("cp.async.commit_group;" ::: "memory");                   \
    }

    FA_PREFETCH(0);

    for (int ch = 0; ch < 32; ch++) {
        if (ch < 31) {
            FA_PREFETCH(ch + 1);
            asm volatile("cp.async.wait_group 1;" ::: "memory");
        } else {
            asm volatile("cp.async.wait_group 0;" ::: "memory");
        }
        __syncthreads();

        const char* kb_ = sbuf + (ch & 1) * 16384;
        const char* vb_ = kb_ + 8192;

        // ---- QK ----
        float sc[8][4];
#pragma unroll
        for (int nb = 0; nb < 8; nb++) {
            sc[nb][0] = sc[nb][1] = sc[nb][2] = sc[nb][3] = 0.f;
#pragma unroll
            for (int kb = 0; kb < 4; kb++) {
                uint2 bb = *(const uint2*)(kb_ + ((nb << 2) | kb) * 256 + lane * 8);
                mma16816h(sc[nb], qa[kb][0], qa[kb][1], qa[kb][2], qa[kb][3],
                          bb.x, bb.y);
            }
        }

        // ---- online softmax (log2 domain) ----
        float cm0 = mx0, cm1 = mx1;
#pragma unroll
        for (int nb = 0; nb < 8; nb++) {
            cm0 = fmaxf(cm0, fmaxf(sc[nb][0], sc[nb][1]));
            cm1 = fmaxf(cm1, fmaxf(sc[nb][2], sc[nb][3]));
        }
        cm0 = fmaxf(cm0, __shfl_xor_sync(0xffffffffu, cm0, 1));
        cm0 = fmaxf(cm0, __shfl_xor_sync(0xffffffffu, cm0, 2));
        cm1 = fmaxf(cm1, __shfl_xor_sync(0xffffffffu, cm1, 1));
        cm1 = fmaxf(cm1, __shfl_xor_sync(0xffffffffu, cm1, 2));
        float corr0 = ex2(mx0 - cm0), corr1 = ex2(mx1 - cm1);
        mx0 = cm0; mx1 = cm1;
        float sum0 = 0.f, sum1 = 0.f;
#pragma unroll
        for (int nb = 0; nb < 8; nb++) {
            sc[nb][0] = ex2(sc[nb][0] - mx0); sum0 += sc[nb][0];
            sc[nb][1] = ex2(sc[nb][1] - mx0); sum0 += sc[nb][1];
            sc[nb][2] = ex2(sc[nb][2] - mx1); sum1 += sc[nb][2];
            sc[nb][3] = ex2(sc[nb][3] - mx1); sum1 += sc[nb][3];
        }
        sum0 += __shfl_xor_sync(0xffffffffu, sum0, 1);
        sum0 += __shfl_xor_sync(0xffffffffu, sum0, 2);
        sum1 += __shfl_xor_sync(0xffffffffu, sum1, 1);
        sum1 += __shfl_xor_sync(0xffffffffu, sum1, 2);
        l0 = l0 * corr0 + sum0;
        l1 = l1 * corr1 + sum1;
#pragma unroll
        for (int nb = 0; nb < 8; nb++) {
            oc[nb][0] *= corr0; oc[nb][1] *= corr0;
            oc[nb][2] *= corr1; oc[nb][3] *= corr1;
        }

        // ---- PV ----
#pragma unroll
        for (int kt = 0; kt < 4; kt++) {
            uint32_t pa0 = pkf16(sc[2 * kt][0],     sc[2 * kt][1]);
            uint32_t pa1 = pkf16(sc[2 * kt][2],     sc[2 * kt][3]);
            uint32_t pa2 = pkf16(sc[2 * kt + 1][0], sc[2 * kt + 1][1]);
            uint32_t pa3 = pkf16(sc[2 * kt + 1][2], sc[2 * kt + 1][3]);
#pragma unroll
            for (int nb = 0; nb < 8; nb++) {
                uint2 vv = *(const uint2*)(vb_ + ((nb << 2) | kt) * 256 + lane * 8);
                mma16816h(oc[nb], pa0, pa1, pa2, pa3, vv.x, vv.y);
            }
        }

        if (ch < 31) __syncthreads();
    }

    // ---- epilogue: write packed-A hi/lo bf16 fragments ----
    const float inv0 = 1.f / l0;
    const float inv1 = 1.f / l1;
    uint32_t* Areg = AOpk + (size_t)(b * 16 + qt) * 32 * 4096;
#pragma unroll
    for (int nb = 0; nb < 8; nb++) {
        int kpair = h * 2 + (nb >> 2);
        int kb = (nb >> 1) & 1;
        uint32_t* base = Areg + (size_t)kpair * 4096 + (wid * 2 + kb) * 256 + lane * 4;
        int i01 = (nb & 1) ? 2 : 0;
        int i23 = (nb & 1) ? 3 : 1;
        uint2 w01 = split2(oc[nb][0] * inv0, oc[nb][1] * inv0);
        uint2 w23 = split2(oc[nb][2] * inv1, oc[nb][3] * inv1);
        base[i01]       = w01.x;
        base[128 + i01] = w01.y;
        base[i23]       = w23.x;
        base[128 + i23] = w23.y;
    }
#undef FA_PREFETCH
}

// ---------------------------------------------------------------------------
// Launch
// ---------------------------------------------------------------------------
extern "C" void kernel_launch(void* const* d_in, const int* in_sizes, int n_in,
                              void* d_out, int out_size)
{
    const float* X   = (const float*)d_in[0];
    const float* R   = (const float*)d_in[1];
    const float* ent = (const float*)d_in[2];
    const float* Wq  = (const float*)d_in[3];
    const float* Wk  = (const float*)d_in[4];
    const float* Wv  = (const float*)d_in[5];
    const float* Wo  = (const float*)d_in[6];
    float* out = (float*)d_out;

    float *wfoldT, *qkv, *rt, *wt;
    uint32_t *kh, *vh, *xpk, *aopk, *wfpk, *wopk;
    cudaGetSymbolAddress((void**)&wfoldT, g_WfoldT);
    cudaGetSymbolAddress((void**)&qkv,    g_QKV);
    cudaGetSymbolAddress((void**)&rt,     g_RT);
    cudaGetSymbolAddress((void**)&wt,     g_WT);
    cudaGetSymbolAddress((void**)&kh,     g_Kh);
    cudaGetSymbolAddress((void**)&vh,     g_Vh);
    cudaGetSymbolAddress((void**)&xpk,    g_Xpk);
    cudaGetSymbolAddress((void**)&aopk,   g_AOpk);
    cudaGetSymbolAddress((void**)&wfpk,   g_Wfpk);
    cudaGetSymbolAddress((void**)&wopk,   g_Wopk);

    static int smem_set = 0;
    if (!smem_set) {
        cudaFuncSetAttribute(tc_gemm_kernel,
                             cudaFuncAttributeMaxDynamicSharedMemorySize, TCB_SMEM);
        cudaFuncSetAttribute(pk_gemm,
                             cudaFuncAttributeMaxDynamicSharedMemorySize, PKG_SMEM);
        smem_set = 1;
    }

    // 1) Transposes: RT = R^T, WT_i = W_i^T
    {
        dim3 g(32, 32, 4);
        transpose_kernel<<<g, 256>>>(R, Wq, Wk, Wv, rt, wt);
    }

    // 2) Folds (batched): WfoldT_i = R^T W_i  (fp32 out)
    {
        dim3 g(8, 8, 3);
        tc_gemm_kernel<<<g, 256, TCB_SMEM>>>(rt, wt, wfoldT, DD,
                                             0, (size_t)DD * DD, (size_t)DD * DD);
    }

    // 3) Pack operands: X (A-side), WfoldT + Wo (B-side)
    pack_a_kernel<<<dim3(32, 32), 256>>>(X, xpk);
    pack_b_kernel<<<dim3(32, 24), 256>>>(wfoldT, wfpk);
    pack_b_kernel<<<dim3(32,  8), 256>>>(Wo, wopk);

    // 4) Fused QKV projection (packed-operand GEMM): QKV = X @ WfoldT^T
    {
        dim3 g(24, 32);
        pk_gemm<<<g, 256, PKG_SMEM>>>(xpk, wfpk, qkv, QKV_LD);
    }

    // 5) Pack K/V fp16 fragment layout for attention
    {
        dim3 g(32, HH, BB);
        pack_kv_kernel<<<g, 256>>>(qkv, kh, vh);
    }

    // 6) Flash attention (epilogue writes packed AO)
    {
        dim3 g(LL / 128, HH, BB);
        flash_attn_tc2<<<g, 256>>>(qkv, kh, vh, ent, aopk);
    }

    // 7) Output projection (packed-operand GEMM): out = AO @ Wo^T
    {
        dim3 g(8, 32);
        pk_gemm<<<g, 256, PKG_SMEM>>>(aopk, wopk, out, DD);
    }
}

// round 8
// speedup vs baseline: 5.9515x; 1.0643x over previous
#include <cuda_runtime.h>
#include <cuda_bf16.h>
#include <math.h>
#include <stdint.h>

// Problem constants
#define BB   2
#define LL   2048
#define DD   1024
#define HH   16
#define HD   64
#define MM   (BB*LL)          // 4096
#define QKV_LD (3*DD)         // fused QKV row stride

// Scratch (static device memory -- no allocations allowed)
__device__ float g_WfoldT[3 * DD * DD];   // R^T @ W_i  fp32 ([n][k])
__device__ float g_QKV[MM * 3 * DD];      // fused [M][3072]: Q | K | V
__device__ float g_RT[DD * DD];           // R^T
__device__ float g_WT[3 * DD * DD];       // W_i^T
// fp16 fragment-layout K/V for attention: per (b,h,chunk64) 32 blocks of 256B
__device__ uint32_t g_Kh[BB * HH * 32 * 32 * 64];   // 8MB
__device__ uint32_t g_Vh[BB * HH * 32 * 32 * 64];   // 8MB
// packed GEMM operands
// A-pack (single f16): region per (mtile,kpair) = 8KB = 16 blocks x 512B
// B-pack (split f16):  region per (ntile,kpair) = 16KB = 32 blocks x [hi256|lo256]
__device__ uint32_t g_Xpk [32 * 32 * 2048];   // X packed f16 (8MB)
__device__ uint32_t g_AOpk[32 * 32 * 2048];   // attention out packed f16 (8MB)
__device__ uint32_t g_Wfpk[24 * 32 * 4096];   // WfoldT packed hi/lo f16 (12MB)
__device__ uint32_t g_Wopk[ 8 * 32 * 4096];   // Wo packed hi/lo f16 (4MB)

// ===========================================================================
// helpers
// ===========================================================================
__device__ __forceinline__ uint32_t pkf16(float lo, float hi) {
    uint32_t r;
    asm("cvt.rn.f16x2.f32 %0, %1, %2;" : "=r"(r) : "f"(hi), "f"(lo));
    return r;
}

__device__ __forceinline__ void unpkf16(float& lo, float& hi, uint32_t w) {
    asm("{.reg .b16 l, h; mov.b32 {l, h}, %2; cvt.f32.f16 %0, l; cvt.f32.f16 %1, h;}"
        : "=f"(lo), "=f"(hi) : "r"(w));
}

// split fp32x4 -> (hi f16x2 pair, lo f16x2 pair)
__device__ __forceinline__ uint4 split4h(float4 v) {
    uint32_t h01 = pkf16(v.x, v.y);
    uint32_t h23 = pkf16(v.z, v.w);
    float f0, f1, f2, f3;
    unpkf16(f0, f1, h01);
    unpkf16(f2, f3, h23);
    uint32_t l01 = pkf16(v.x - f0, v.y - f1);
    uint32_t l23 = pkf16(v.z - f2, v.w - f3);
    return make_uint4(h01, h23, l01, l23);
}

// bf16 split (folds only)
__device__ __forceinline__ uint4 split4(float4 v) {
    uint32_t h01, h23;
    asm("cvt.rn.bf16x2.f32 %0, %1, %2;" : "=r"(h01) : "f"(v.y), "f"(v.x));
    asm("cvt.rn.bf16x2.f32 %0, %1, %2;" : "=r"(h23) : "f"(v.w), "f"(v.z));
    float h0 = __uint_as_float(h01 << 16);
    float h1 = __uint_as_float(h01 & 0xFFFF0000u);
    float h2 = __uint_as_float(h23 << 16);
    float h3 = __uint_as_float(h23 & 0xFFFF0000u);
    uint32_t l01, l23;
    asm("cvt.rn.bf16x2.f32 %0, %1, %2;" : "=r"(l01) : "f"(v.y - h1), "f"(v.x - h0));
    asm("cvt.rn.bf16x2.f32 %0, %1, %2;" : "=r"(l23) : "f"(v.w - h3), "f"(v.z - h2));
    return make_uint4(h01, h23, l01, l23);
}

__device__ __forceinline__ void mma16816(float* c,
                                         uint32_t a0, uint32_t a1, uint32_t a2, uint32_t a3,
                                         uint32_t b0, uint32_t b1) {
    asm volatile(
        "mma.sync.aligned.m16n8k16.row.col.f32.bf16.bf16.f32 "
        "{%0,%1,%2,%3}, {%4,%5,%6,%7}, {%8,%9}, {%0,%1,%2,%3};"
        : "+f"(c[0]), "+f"(c[1]), "+f"(c[2]), "+f"(c[3])
        : "r"(a0), "r"(a1), "r"(a2), "r"(a3), "r"(b0), "r"(b1));
}

__device__ __forceinline__ void mma16816h(float* c,
                                          uint32_t a0, uint32_t a1, uint32_t a2, uint32_t a3,
                                          uint32_t b0, uint32_t b1) {
    asm volatile(
        "mma.sync.aligned.m16n8k16.row.col.f32.f16.f16.f32 "
        "{%0,%1,%2,%3}, {%4,%5,%6,%7}, {%8,%9}, {%0,%1,%2,%3};"
        : "+f"(c[0]), "+f"(c[1]), "+f"(c[2]), "+f"(c[3])
        : "r"(a0), "r"(a1), "r"(a2), "r"(a3), "r"(b0), "r"(b1));
}

__device__ __forceinline__ float ex2(float x) {
    float r;
    asm("ex2.approx.f32 %0, %1;" : "=f"(r) : "f"(x));
    return r;
}

__device__ __forceinline__ uint32_t ex2h2(uint32_t x) {
    uint32_t r;
    asm("ex2.approx.f16x2 %0, %1;" : "=r"(r) : "r"(x));
    return r;
}

__device__ __forceinline__ uint32_t smem_u32(const void* p) {
    uint32_t a;
    asm("{ .reg .u64 t; cvta.to.shared.u64 t, %1; cvt.u32.u64 %0, t; }"
        : "=r"(a) : "l"(p));
    return a;
}

__device__ __forceinline__ void cp_async16(uint32_t dst, const void* src) {
    asm volatile("cp.async.cg.shared.global [%0], [%1], 16;"
                 :: "r"(dst), "l"(src) : "memory");
}

// ===========================================================================
// Operand pack kernels
// ===========================================================================
// A-pack: single f16, region (mtile,kpair) = 2048 words
__global__ __launch_bounds__(256)
void pack_a_kernel(const float* __restrict__ src, uint32_t* __restrict__ dst)
{
    const int kpair = blockIdx.x, mtile = blockIdx.y, tid = threadIdx.x;
    uint32_t* region = dst + ((size_t)mtile * 32 + kpair) * 2048;
#pragma unroll
    for (int i = 0; i < 4; i++) {
        int idx = i * 256 + tid;
        int row = idx >> 3, c4 = (idx & 7) << 2;
        float4 v = *reinterpret_cast<const float4*>(
            &src[(size_t)(mtile * 128 + row) * 1024 + kpair * 32 + c4]);
        uint32_t w0 = pkf16(v.x, v.y);
        uint32_t w1 = pkf16(v.z, v.w);
        int mb = row >> 4, r = row & 7;
        int islow = ((row & 15) < 8);
        int kb = c4 >> 4, kk = c4 & 15;
        int khigh = (kk >> 3) & 1, t = (kk & 7) >> 1;
        uint32_t* base = region + (mb * 2 + kb) * 128;
        int aidx = islow ? (khigh ? 2 : 0) : (khigh ? 3 : 1);
        base[(r * 4 + t)     * 4 + aidx] = w0;
        base[(r * 4 + t + 1) * 4 + aidx] = w1;
    }
}

// B-pack: split hi/lo f16, region (ntile,kpair) = 4096 words
__global__ __launch_bounds__(256)
void pack_b_kernel(const float* __restrict__ src, uint32_t* __restrict__ dst)
{
    const int kpair = blockIdx.x, ntile = blockIdx.y, tid = threadIdx.x;
    uint32_t* region = dst + ((size_t)ntile * 32 + kpair) * 4096;
#pragma unroll
    for (int i = 0; i < 4; i++) {
        int idx = i * 256 + tid;
        int row = idx >> 3, c4 = (idx & 7) << 2;
        float4 v = *reinterpret_cast<const float4*>(
            &src[(size_t)(ntile * 128 + row) * 1024 + kpair * 32 + c4]);
        uint4 sp = split4h(v);
        int nb = row >> 3;
        int kb = c4 >> 4, kk = c4 & 15;
        int khigh = (kk >> 3) & 1, t = (kk & 7) >> 1;
        int L = ((row & 7) << 2) + t;
        uint32_t* base = region + (nb * 2 + kb) * 128;
        base[L * 2 + khigh]            = sp.x;
        base[(L + 1) * 2 + khigh]      = sp.y;
        base[64 + L * 2 + khigh]       = sp.z;
        base[64 + (L + 1) * 2 + khigh] = sp.w;
    }
}

// ===========================================================================
// Packed 2-pass f16 GEMM: C[M,N] = A @ (Bhi+Blo)^T, K=1024.
// A single f16 fragments, B split hi/lo f16 fragments, cp.async streamed.
// Grid (ntile, mtile), 256 thr = 8 warps (2x4) of 64x32 tiles, BK=32, 2 bufs.
// ===========================================================================
#define PKG_SMEM 49152

__global__ __launch_bounds__(256)
void pk_gemm(const uint32_t* __restrict__ A, const uint32_t* __restrict__ B,
             float* __restrict__ C, int ldc)
{
    extern __shared__ char sm[];
    const uint32_t sb = smem_u32(sm);
    const int tid  = threadIdx.x;
    const int lane = tid & 31;
    const int wid  = tid >> 5;
    const int wm   = (wid >> 2) * 64;
    const int wn   = (wid & 3) * 32;

    const char* Ag = reinterpret_cast<const char*>(A + (size_t)blockIdx.y * 32 * 2048);
    const char* Bg = reinterpret_cast<const char*>(B + (size_t)blockIdx.x * 32 * 4096);

    float acc[4][4][4];
#pragma unroll
    for (int i = 0; i < 4; i++)
#pragma unroll
        for (int j = 0; j < 4; j++)
#pragma unroll
            for (int q = 0; q < 4; q++) acc[i][j][q] = 0.f;

#define PKG_PF(ch)                                                             \
    {                                                                          \
        uint32_t d = sb + ((ch) & 1) * 24576;                                  \
        const char* a = Ag + (size_t)(ch) * 8192 + tid * 32;                   \
        const char* b = Bg + (size_t)(ch) * 16384 + tid * 64;                  \
        cp_async16(d + tid * 32,      a);                                      \
        cp_async16(d + tid * 32 + 16, a + 16);                                 \
        uint32_t db = d + 8192 + tid * 64;                                     \
        cp_async16(db,      b);                                                \
        cp_async16(db + 16, b + 16);                                           \
        cp_async16(db + 32, b + 32);                                           \
        cp_async16(db + 48, b + 48);                                           \
        asm volatile("cp.async.commit_group;" ::: "memory");                   \
    }

    PKG_PF(0);

    for (int ch = 0; ch < 32; ch++) {
        if (ch < 31) {
            PKG_PF(ch + 1);
            asm volatile("cp.async.wait_group 1;" ::: "memory");
        } else {
            asm volatile("cp.async.wait_group 0;" ::: "memory");
        }
        __syncthreads();

        const char* bufA = sm + (ch & 1) * 24576;
        const char* bufB = bufA + 8192;
#pragma unroll
        for (int kb = 0; kb < 2; kb++) {
            uint4 ah[4];
            uint2 bh[4], bl[4];
#pragma unroll
            for (int am = 0; am < 4; am++) {
                const char* p = bufA + ((((wm >> 4) + am) * 2 + kb) << 9) + lane * 16;
                ah[am] = *(const uint4*)p;
            }
#pragma unroll
            for (int bn = 0; bn < 4; bn++) {
                const char* q = bufB + ((((wn >> 3) + bn) * 2 + kb) << 9) + lane * 8;
                bh[bn] = *(const uint2*)q;
                bl[bn] = *(const uint2*)(q + 256);
            }
#pragma unroll
            for (int am = 0; am < 4; am++)
#pragma unroll
                for (int bn = 0; bn < 4; bn++) {
                    float* c = acc[am][bn];
                    mma16816h(c, ah[am].x, ah[am].y, ah[am].z, ah[am].w,
                              bh[bn].x, bh[bn].y);
                    mma16816h(c, ah[am].x, ah[am].y, ah[am].z, ah[am].w,
                              bl[bn].x, bl[bn].y);
                }
        }
        if (ch < 31) __syncthreads();
    }

    const int m0 = blockIdx.y * 128;
    const int n0 = blockIdx.x * 128;
#pragma unroll
    for (int am = 0; am < 4; am++)
#pragma unroll
        for (int bn = 0; bn < 4; bn++) {
            const float* c = acc[am][bn];
            int row = m0 + wm + am * 16 + (lane >> 2);
            int col = n0 + wn + bn * 8 + ((lane & 3) << 1);
            *reinterpret_cast<float2*>(&C[(size_t)row * ldc + col]) =
                make_float2(c[0], c[1]);
            *reinterpret_cast<float2*>(&C[(size_t)(row + 8) * ldc + col]) =
                make_float2(c[2], c[3]);
        }
#undef PKG_PF
}

// ===========================================================================
// Convert-in-kernel split-bf16 GEMM — weight folds only (exact-ish, 1.5e-5).
// ===========================================================================
#define TCB_SMEM 65536

__global__ __launch_bounds__(256, 1)
void tc_gemm_kernel(const float* __restrict__ A, const float* __restrict__ B,
                    float* __restrict__ C, int ldc,
                    size_t sA, size_t sB, size_t sC)
{
    extern __shared__ char sm[];
    A += blockIdx.z * sA;
    B += blockIdx.z * sB;
    C += blockIdx.z * sC;
    const int tid  = threadIdx.x;
    const int lane = tid & 31;
    const int wid  = tid >> 5;
    const int wm   = (wid >> 2) * 64;
    const int wn   = (wid & 3) * 32;
    const int m0 = blockIdx.y * 128;
    const int n0 = blockIdx.x * 128;
    const int pl = lane ^ (lane >> 3);

    float acc[4][4][4];
#pragma unroll
    for (int i = 0; i < 4; i++)
#pragma unroll
        for (int j = 0; j < 4; j++)
#pragma unroll
            for (int q = 0; q < 4; q++) acc[i][j][q] = 0.f;

    float4 ra[4], rb[4];

#define LDG_CHUNK(k0)                                                          \
    {                                                                          \
        _Pragma("unroll")                                                      \
        for (int i = 0; i < 4; i++) {                                          \
            int idx = i * 256 + tid;                                           \
            int r = idx >> 3, c4 = (idx & 7) << 2;                             \
            ra[i] = *reinterpret_cast<const float4*>(                          \
                &A[(size_t)(m0 + r) * 1024 + (k0) + c4]);                      \
            rb[i] = *reinterpret_cast<const float4*>(                          \
                &B[(size_t)(n0 + r) * 1024 + (k0) + c4]);                      \
        }                                                                      \
    }

#define STS_CHUNK(bufp)                                                        \
    {                                                                          \
        char* _buf = (bufp);                                                   \
        _Pragma("unroll")                                                      \
        for (int i = 0; i < 4; i++) {                                          \
            int idx = i * 256 + tid;                                           \
            int r = idx >> 3, c4 = (idx & 7) << 2;                             \
            int kb = c4 >> 4, kk = c4 & 15;                                    \
            int rr = r & 15, mb = r >> 4;                                      \
            int s  = ((rr & 7) << 2) + ((kk & 7) >> 1);                        \
            int ps  = s ^ (s >> 3);                                            \
            int ps1 = (s + 1) ^ ((s + 1) >> 3);                                \
            int rg = (kk >> 3) + ((rr >> 3) << 1);                             \
            uint4 sp = split4(ra[i]);                                          \
            char* ab = _buf + (((mb << 1) + kb) << 9) + (rg << 2);             \
            *(uint32_t*)(ab + ps  * 16)        = sp.x;                         \
            *(uint32_t*)(ab + ps1 * 16)        = sp.y;                         \
            *(uint32_t*)(ab + 8192 + ps  * 16) = sp.z;                         \
            *(uint32_t*)(ab + 8192 + ps1 * 16) = sp.w;                         \
            int nn = r & 7, nb = r >> 3;                                       \
            int sb2 = (nn << 2) + ((kk & 7) >> 1);                             \
            int psb  = sb2 ^ (sb2 >> 3);                                       \
            int psb1 = (sb2 + 1) ^ ((sb2 + 1) >> 3);                           \
            int rgb = kk >> 3;                                                 \
            uint4 sq = split4(rb[i]);                                          \
            char* bb = _buf + 16384 + (((nb << 1) + kb) << 9) + (rgb << 2);    \
            *(uint32_t*)(bb + psb  * 16)     = sq.x;                           \
            *(uint32_t*)(bb + psb1 * 16)     = sq.y;                           \
            *(uint32_t*)(bb + psb  * 16 + 8) = sq.z;                           \
            *(uint32_t*)(bb + psb1 * 16 + 8) = sq.w;                           \
        }                                                                      \
    }

#define COMPUTE_CHUNK(bufp)                                                    \
    {                                                                          \
        const char* _buf = (bufp);                                             \
        _Pragma("unroll")                                                      \
        for (int kb = 0; kb < 2; kb++) {                                       \
            uint4 ah[4], al[4], bq[4];                                         \
            _Pragma("unroll")                                                  \
            for (int am = 0; am < 4; am++) {                                   \
                const char* p = _buf + (((((wm >> 4) + am) << 1) + kb) << 9)   \
                                + pl * 16;                                     \
                ah[am] = *(const uint4*)p;                                     \
                al[am] = *(const uint4*)(p + 8192);                            \
            }                                                                  \
            _Pragma("unroll")                                                  \
            for (int bn = 0; bn < 4; bn++) {                                   \
                const char* p = _buf + 16384                                   \
                                + (((((wn >> 3) + bn) << 1) + kb) << 9)        \
                                + pl * 16;                                     \
                bq[bn] = *(const uint4*)p;                                     \
            }                                                                  \
            _Pragma("unroll")                                                  \
            for (int am = 0; am < 4; am++)                                     \
                _Pragma("unroll")                                              \
                for (int bn = 0; bn < 4; bn++) {                               \
                    float* c = acc[am][bn];                                    \
                    mma16816(c, ah[am].x, ah[am].z, ah[am].y, ah[am].w,        \
                             bq[bn].x, bq[bn].y);                              \
                    mma16816(c, ah[am].x, ah[am].z, ah[am].y, ah[am].w,        \
                             bq[bn].z, bq[bn].w);                              \
                    mma16816(c, al[am].x, al[am].z, al[am].y, al[am].w,        \
                             bq[bn].x, bq[bn].y);                              \
                }                                                              \
        }                                                                      \
    }

    LDG_CHUNK(0);
    STS_CHUNK(sm);
    __syncthreads();

    for (int ch = 0; ch < 32; ch++) {
        if (ch < 31) LDG_CHUNK((ch + 1) * 32);
        COMPUTE_CHUNK(sm + (ch & 1) * 32768);
        if (ch < 31) {
            STS_CHUNK(sm + ((ch + 1) & 1) * 32768);
            __syncthreads();
        }
    }

#pragma unroll
    for (int am = 0; am < 4; am++)
#pragma unroll
        for (int bn = 0; bn < 4; bn++) {
            const float* c = acc[am][bn];
            int row = m0 + wm + am * 16 + (lane >> 2);
            int col = n0 + wn + bn * 8 + ((lane & 3) << 1);
            *reinterpret_cast<float2*>(&C[(size_t)row * ldc + col]) =
                make_float2(c[0], c[1]);
            *reinterpret_cast<float2*>(&C[(size_t)(row + 8) * ldc + col]) =
                make_float2(c[2], c[3]);
        }
#undef LDG_CHUNK
#undef STS_CHUNK
#undef COMPUTE_CHUNK
}

// ---------------------------------------------------------------------------
// Batched 1024x1024 transpose: z=0 -> RT = R^T; z=1..3 -> WT_i = W_i^T
// ---------------------------------------------------------------------------
__global__ __launch_bounds__(256)
void transpose_kernel(const float* __restrict__ R,
                      const float* __restrict__ Wq,
                      const float* __restrict__ Wk,
                      const float* __restrict__ Wv,
                      float* __restrict__ RT, float* __restrict__ WT)
{
    __shared__ float t[32][33];
    const int z = blockIdx.z;
    const float* src = (z == 0) ? R : (z == 1) ? Wq : (z == 2) ? Wk : Wv;
    float* dst = (z == 0) ? RT : (WT + (size_t)(z - 1) * DD * DD);

    const int x0 = blockIdx.x * 32;
    const int y0 = blockIdx.y * 32;
    const int tx = threadIdx.x & 31;
    const int ty = threadIdx.x >> 5;

#pragma unroll
    for (int i = 0; i < 4; i++)
        t[ty + i * 8][tx] = src[(size_t)(y0 + ty + i * 8) * DD + x0 + tx];
    __syncthreads();
#pragma unroll
    for (int i = 0; i < 4; i++)
        dst[(size_t)(x0 + ty + i * 8) * DD + y0 + tx] = t[tx][ty + i * 8];
}

// ---------------------------------------------------------------------------
// Pack K,V (fp32 in g_QKV) into fp16 fragment-layout global blocks.
// ---------------------------------------------------------------------------
__global__ __launch_bounds__(256)
void pack_kv_kernel(const float* __restrict__ QKV,
                    uint32_t* __restrict__ Kh, uint32_t* __restrict__ Vh)
{
    __shared__ float st[64 * 72];
    const int ch = blockIdx.x, h = blockIdx.y, b = blockIdx.z;
    const int tid = threadIdx.x;
    const size_t rowbase = (size_t)(b * LL + ch * 64) * QKV_LD;
    const int grp = ((b * HH + h) * 32 + ch) * 32;

    // ---- K ----
#pragma unroll
    for (int i = 0; i < 4; i++) {
        int idx = i * 256 + tid;
        int key = idx >> 4, c4 = (idx & 15) << 2;
        *reinterpret_cast<float4*>(&st[key * 72 + c4]) =
            *reinterpret_cast<const float4*>(
                &QKV[rowbase + (size_t)key * QKV_LD + DD + h * HD + c4]);
    }
    __syncthreads();
#pragma unroll
    for (int i = 0; i < 8; i++) {
        int wi = i * 256 + tid;
        int key = wi >> 5, d2 = wi & 31, d = d2 * 2;
        uint32_t word = pkf16(st[key * 72 + d], st[key * 72 + d + 1]);
        int nb = key >> 3, kb = d >> 4;
        int L = ((key & 7) << 2) | (d2 & 3);
        int w = (d2 >> 2) & 1;
        Kh[(size_t)(grp + nb * 4 + kb) * 64 + L * 2 + w] = word;
    }
    __syncthreads();

    // ---- V ----
#pragma unroll
    for (int i = 0; i < 4; i++) {
        int idx = i * 256 + tid;
        int key = idx >> 4, c4 = (idx & 15) << 2;
        *reinterpret_cast<float4*>(&st[key * 72 + c4]) =
            *reinterpret_cast<const float4*>(
                &QKV[rowbase + (size_t)key * QKV_LD + 2 * DD + h * HD + c4]);
    }
    __syncthreads();
#pragma unroll
    for (int i = 0; i < 8; i++) {
        int wi = i * 256 + tid;
        int dim = wi >> 5, kp = wi & 31, key = kp * 2;
        uint32_t word = pkf16(st[key * 72 + dim], st[(key + 1) * 72 + dim]);
        int nb = dim >> 3, kt = kp >> 3;
        int p = kp & 7;
        int L = ((dim & 7) << 2) | (p & 3);
        int w = p >> 2;
        Vh[(size_t)(grp + nb * 4 + kt) * 64 + L * 2 + w] = word;
    }
}

// ===========================================================================
// Tensor-core flash attention: packed fp16 K/V via cp.async.
// Softmax-lite: f16x2 ex2 producing P fragments directly; row sums via
// ones-vector MMA (no shuffle sum). Epilogue writes f16 packed-A AO.
// ===========================================================================
#define ONES16X2 0x3C003C00u

__global__ __launch_bounds__(256, 2)
void flash_attn_tc2(const float* __restrict__ QKV,
                    const uint32_t* __restrict__ Kh,
                    const uint32_t* __restrict__ Vh,
                    const float* __restrict__ entangle,
                    uint32_t* __restrict__ AOpk)
{
    __shared__ char sbuf[2 * 16384];
    const uint32_t sb0 = smem_u32(sbuf);

    const int b  = blockIdx.z;
    const int h  = blockIdx.y;
    const int qt = blockIdx.x;
    const int tid  = threadIdx.x;
    const int lane = tid & 31;
    const int wid  = tid >> 5;
    const int t = lane & 3;
    const int r = lane >> 2;

    const float scale = entangle[h] * 0.125f * 1.44269504f;

    // ---- Q fragments ----
    const int mrow = b * LL + qt * 128 + wid * 16 + r;
    const float* q0p = QKV + (size_t)mrow * QKV_LD + h * HD;
    const float* q8p = q0p + (size_t)8 * QKV_LD;
    uint32_t qa[4][4];
#pragma unroll
    for (int kb = 0; kb < 4; kb++) {
        const int c = kb * 16 + 2 * t;
        float2 v0a = *reinterpret_cast<const float2*>(q0p + c);
        float2 v8a = *reinterpret_cast<const float2*>(q8p + c);
        float2 v0b = *reinterpret_cast<const float2*>(q0p + c + 8);
        float2 v8b = *reinterpret_cast<const float2*>(q8p + c + 8);
        qa[kb][0] = pkf16(v0a.x * scale, v0a.y * scale);
        qa[kb][1] = pkf16(v8a.x * scale, v8a.y * scale);
        qa[kb][2] = pkf16(v0b.x * scale, v0b.y * scale);
        qa[kb][3] = pkf16(v8b.x * scale, v8b.y * scale);
    }

    float oc[8][4];
#pragma unroll
    for (int i = 0; i < 8; i++)
#pragma unroll
        for (int j = 0; j < 4; j++) oc[i][j] = 0.f;
    float l0 = 0.f, l1 = 0.f;
    float mx0 = -1e30f, mx1 = -1e30f;

    const char* Kg = reinterpret_cast<const char*>(Kh)
                     + (size_t)((b * HH + h) * 32) * 8192;
    const char* Vg = reinterpret_cast<const char*>(Vh)
                     + (size_t)((b * HH + h) * 32) * 8192;

#define FA_PREFETCH(ch)                                                        \
    {                                                                          \
        uint32_t d = sb0 + ((ch) & 1) * 16384 + tid * 16;                      \
        const char* ks = Kg + (size_t)(ch) * 8192 + tid * 16;                  \
        const char* vs = Vg + (size_t)(ch) * 8192 + tid * 16;                  \
        cp_async16(d,           ks);                                           \
        cp_async16(d + 4096,    ks + 4096);                                    \
        cp_async16(d + 8192,    vs);                                           \
        cp_async16(d + 12288,   vs + 4096);                                    \
        asm volatile("cp.async.commit_group;" ::: "memory");                   \
    }

    FA_PREFETCH(0);

    for (int ch = 0; ch < 32; ch++) {
        if (ch < 31) {
            FA_PREFETCH(ch + 1);
            asm volatile("cp.async.wait_group 1;" ::: "memory");
        } else {
            asm volatile("cp.async.wait_group 0;" ::: "memory");
        }
        __syncthreads();

        const char* kb_ = sbuf + (ch & 1) * 16384;
        const char* vb_ = kb_ + 8192;

        // ---- QK ----
        float sc[8][4];
#pragma unroll
        for (int nb = 0; nb < 8; nb++) {
            sc[nb][0] = sc[nb][1] = sc[nb][2] = sc[nb][3] = 0.f;
#pragma unroll
            for (int kb = 0; kb < 4; kb++) {
                uint2 bb = *(const uint2*)(kb_ + ((nb << 2) | kb) * 256 + lane * 8);
                mma16816h(sc[nb], qa[kb][0], qa[kb][1], qa[kb][2], qa[kb][3],
                          bb.x, bb.y);
            }
        }

        // ---- max reduce (f32) ----
        float cm0 = mx0, cm1 = mx1;
#pragma unroll
        for (int nb = 0; nb < 8; nb++) {
            cm0 = fmaxf(cm0, fmaxf(sc[nb][0], sc[nb][1]));
            cm1 = fmaxf(cm1, fmaxf(sc[nb][2], sc[nb][3]));
        }
        cm0 = fmaxf(cm0, __shfl_xor_sync(0xffffffffu, cm0, 1));
        cm0 = fmaxf(cm0, __shfl_xor_sync(0xffffffffu, cm0, 2));
        cm1 = fmaxf(cm1, __shfl_xor_sync(0xffffffffu, cm1, 1));
        cm1 = fmaxf(cm1, __shfl_xor_sync(0xffffffffu, cm1, 2));
        float corr0 = ex2(mx0 - cm0), corr1 = ex2(mx1 - cm1);
        mx0 = cm0; mx1 = cm1;

        // ---- P fragments via f16x2 ex2 (these ARE the PV A-operand words) ----
        uint32_t pw0[8], pw1[8];
#pragma unroll
        for (int nb = 0; nb < 8; nb++) {
            pw0[nb] = ex2h2(pkf16(sc[nb][0] - mx0, sc[nb][1] - mx0));
            pw1[nb] = ex2h2(pkf16(sc[nb][2] - mx1, sc[nb][3] - mx1));
        }

        // ---- row sums via ones-vector MMA ----
        float ls[4] = {0.f, 0.f, 0.f, 0.f};
#pragma unroll
        for (int kt = 0; kt < 4; kt++)
            mma16816h(ls, pw0[2 * kt], pw1[2 * kt],
                      pw0[2 * kt + 1], pw1[2 * kt + 1], ONES16X2, ONES16X2);
        l0 = l0 * corr0 + ls[0];
        l1 = l1 * corr1 + ls[2];

        // ---- rescale accumulators ----
#pragma unroll
        for (int nb = 0; nb < 8; nb++) {
            oc[nb][0] *= corr0; oc[nb][1] *= corr0;
            oc[nb][2] *= corr1; oc[nb][3] *= corr1;
        }

        // ---- PV ----
#pragma unroll
        for (int kt = 0; kt < 4; kt++) {
#pragma unroll
            for (int nb = 0; nb < 8; nb++) {
                uint2 vv = *(const uint2*)(vb_ + ((nb << 2) | kt) * 256 + lane * 8);
                mma16816h(oc[nb], pw0[2 * kt], pw1[2 * kt],
                          pw0[2 * kt + 1], pw1[2 * kt + 1], vv.x, vv.y);
            }
        }

        if (ch < 31) __syncthreads();
    }

    // ---- epilogue: write f16 packed-A fragments ----
    const float inv0 = 1.f / l0;
    const float inv1 = 1.f / l1;
    uint32_t* Areg = AOpk + (size_t)(b * 16 + qt) * 32 * 2048;
#pragma unroll
    for (int nb = 0; nb < 8; nb++) {
        int kpair = h * 2 + (nb >> 2);
        int kb = (nb >> 1) & 1;
        uint32_t* base = Areg + (size_t)kpair * 2048 + (wid * 2 + kb) * 128 + lane * 4;
        int i01 = (nb & 1) ? 2 : 0;
        int i23 = (nb & 1) ? 3 : 1;
        base[i01] = pkf16(oc[nb][0] * inv0, oc[nb][1] * inv0);
        base[i23] = pkf16(oc[nb][2] * inv1, oc[nb][3] * inv1);
    }
#undef FA_PREFETCH
}

// ---------------------------------------------------------------------------
// Launch
// ---------------------------------------------------------------------------
extern "C" void kernel_launch(void* const* d_in, const int* in_sizes, int n_in,
                              void* d_out, int out_size)
{
    const float* X   = (const float*)d_in[0];
    const float* R   = (const float*)d_in[1];
    const float* ent = (const float*)d_in[2];
    const float* Wq  = (const float*)d_in[3];
    const float* Wk  = (const float*)d_in[4];
    const float* Wv  = (const float*)d_in[5];
    const float* Wo  = (const float*)d_in[6];
    float* out = (float*)d_out;

    float *wfoldT, *qkv, *rt, *wt;
    uint32_t *kh, *vh, *xpk, *aopk, *wfpk, *wopk;
    cudaGetSymbolAddress((void**)&wfoldT, g_WfoldT);
    cudaGetSymbolAddress((void**)&qkv,    g_QKV);
    cudaGetSymbolAddress((void**)&rt,     g_RT);
    cudaGetSymbolAddress((void**)&wt,     g_WT);
    cudaGetSymbolAddress((void**)&kh,     g_Kh);
    cudaGetSymbolAddress((void**)&vh,     g_Vh);
    cudaGetSymbolAddress((void**)&xpk,    g_Xpk);
    cudaGetSymbolAddress((void**)&aopk,   g_AOpk);
    cudaGetSymbolAddress((void**)&wfpk,   g_Wfpk);
    cudaGetSymbolAddress((void**)&wopk,   g_Wopk);

    static int smem_set = 0;
    if (!smem_set) {
        cudaFuncSetAttribute(tc_gemm_kernel,
                             cudaFuncAttributeMaxDynamicSharedMemorySize, TCB_SMEM);
        cudaFuncSetAttribute(pk_gemm,
                             cudaFuncAttributeMaxDynamicSharedMemorySize, PKG_SMEM);
        smem_set = 1;
    }

    // 1) Transposes: RT = R^T, WT_i = W_i^T
    {
        dim3 g(32, 32, 4);
        transpose_kernel<<<g, 256>>>(R, Wq, Wk, Wv, rt, wt);
    }

    // 2) Folds (batched): WfoldT_i = R^T W_i  (fp32 out)
    {
        dim3 g(8, 8, 3);
        tc_gemm_kernel<<<g, 256, TCB_SMEM>>>(rt, wt, wfoldT, DD,
                                             0, (size_t)DD * DD, (size_t)DD * DD);
    }

    // 3) Pack operands: X (A-side f16), WfoldT + Wo (B-side split f16)
    pack_a_kernel<<<dim3(32, 32), 256>>>(X, xpk);
    pack_b_kernel<<<dim3(32, 24), 256>>>(wfoldT, wfpk);
    pack_b_kernel<<<dim3(32,  8), 256>>>(Wo, wopk);

    // 4) Fused QKV projection (2-pass f16 GEMM): QKV = X @ WfoldT^T
    {
        dim3 g(24, 32);
        pk_gemm<<<g, 256, PKG_SMEM>>>(xpk, wfpk, qkv, QKV_LD);
    }

    // 5) Pack K/V fp16 fragment layout for attention
    {
        dim3 g(32, HH, BB);
        pack_kv_kernel<<<g, 256>>>(qkv, kh, vh);
    }

    // 6) Flash attention (epilogue writes f16 packed AO)
    {
        dim3 g(LL / 128, HH, BB);
        flash_attn_tc2<<<g, 256>>>(qkv, kh, vh, ent, aopk);
    }

    // 7) Output projection (2-pass f16 GEMM): out = AO @ Wo^T
    {
        dim3 g(8, 32);
        pk_gemm<<<g, 256, PKG_SMEM>>>(aopk, wopk, out, DD);
    }
}